// round 8
// baseline (speedup 1.0000x reference)
#include <cuda_runtime.h>
#include <cuda_bf16.h>
#include <cuda_fp16.h>
#include <math.h>
#include <stdint.h>

// Problem constants
#define BATCH 2
#define SEQ   2048
#define ISZ   1024
#define NHEAD 16
#define HDIM  64
#define ROWS  (BATCH*SEQ)      // 4096

typedef __nv_bfloat16 bf16;

// ---------------------------------------------------------------------------
// Scratch (device globals: allocation-free per harness rules)
// ---------------------------------------------------------------------------
__device__ bf16  g_xhi[(size_t)3*ROWS*ISZ];   // LN outputs hi (q,k,v)
__device__ bf16  g_xlo[(size_t)3*ROWS*ISZ];   // LN outputs lo
__device__ bf16  g_wth[(size_t)4*ISZ*ISZ];    // W^T hi (Wq,Wk,Wv,Wo)
__device__ bf16  g_wtl[(size_t)4*ISZ*ISZ];    // W^T lo
__device__ float g_qw[(size_t)ROWS*ISZ];
__device__ float g_kw[(size_t)ROWS*ISZ];
__device__ float g_vw[(size_t)ROWS*ISZ];
__device__ bf16  g_aoh[(size_t)ROWS*ISZ];     // attention out hi
__device__ bf16  g_aol[(size_t)ROWS*ISZ];     // attention out lo

// ---------------------------------------------------------------------------
// PTX helpers (Ampere-compatible: cp.async, ldmatrix, mma.sync)
// ---------------------------------------------------------------------------
__device__ __forceinline__ uint32_t smem_u32(const void* p) {
    return (uint32_t)__cvta_generic_to_shared(p);
}
__device__ __forceinline__ void cp_async16(uint32_t dst, const void* src) {
    asm volatile("cp.async.cg.shared.global [%0], [%1], 16;\n" :: "r"(dst), "l"(src));
}
__device__ __forceinline__ void cp_commit() {
    asm volatile("cp.async.commit_group;\n");
}
__device__ __forceinline__ void cp_wait1() {
    asm volatile("cp.async.wait_group 1;\n");
}
__device__ __forceinline__ void cp_wait0() {
    asm volatile("cp.async.wait_group 0;\n");
}
__device__ __forceinline__ void ldsm_x4(uint32_t& r0, uint32_t& r1,
                                        uint32_t& r2, uint32_t& r3, uint32_t a) {
    asm volatile("ldmatrix.sync.aligned.m8n8.x4.shared.b16 {%0,%1,%2,%3}, [%4];"
                 : "=r"(r0), "=r"(r1), "=r"(r2), "=r"(r3) : "r"(a));
}
__device__ __forceinline__ void ldsm_x2(uint32_t& r0, uint32_t& r1, uint32_t a) {
    asm volatile("ldmatrix.sync.aligned.m8n8.x2.shared.b16 {%0,%1}, [%2];"
                 : "=r"(r0), "=r"(r1) : "r"(a));
}
__device__ __forceinline__ void ldsm_x2t(uint32_t& r0, uint32_t& r1, uint32_t a) {
    asm volatile("ldmatrix.sync.aligned.m8n8.x2.trans.shared.b16 {%0,%1}, [%2];"
                 : "=r"(r0), "=r"(r1) : "r"(a));
}
__device__ __forceinline__ void mma_bf16(float* d, const uint32_t* a, const uint32_t* b) {
    asm volatile("mma.sync.aligned.m16n8k16.row.col.f32.bf16.bf16.f32 "
                 "{%0,%1,%2,%3}, {%4,%5,%6,%7}, {%8,%9}, {%0,%1,%2,%3};"
                 : "+f"(d[0]), "+f"(d[1]), "+f"(d[2]), "+f"(d[3])
                 : "r"(a[0]), "r"(a[1]), "r"(a[2]), "r"(a[3]), "r"(b[0]), "r"(b[1]));
}
__device__ __forceinline__ void mma_f16(float* d, const uint32_t* a, const uint32_t* b) {
    asm volatile("mma.sync.aligned.m16n8k16.row.col.f32.f16.f16.f32 "
                 "{%0,%1,%2,%3}, {%4,%5,%6,%7}, {%8,%9}, {%0,%1,%2,%3};"
                 : "+f"(d[0]), "+f"(d[1]), "+f"(d[2]), "+f"(d[3])
                 : "r"(a[0]), "r"(a[1]), "r"(a[2]), "r"(a[3]), "r"(b[0]), "r"(b[1]));
}
__device__ __forceinline__ uint32_t h2pack(float a, float b) {
    __half2 h = __floats2half2_rn(a, b);
    return *(uint32_t*)&h;
}

// ---------------------------------------------------------------------------
// LayerNorm: one block per row; writes split-bf16 (hi, lo)
// ---------------------------------------------------------------------------
__global__ __launch_bounds__(256) void ln3_kernel(
    const float* __restrict__ q, const float* __restrict__ k,
    const float* __restrict__ v, const float* __restrict__ g,
    const float* __restrict__ beta)
{
    __shared__ float sbuf[8];
    int which = blockIdx.x >> 12;
    int row   = blockIdx.x & 4095;
    const float* x =
        (which == 0 ? q : which == 1 ? k : v) + (size_t)row * ISZ;
    bf16* ohi = g_xhi + (size_t)which * ROWS * ISZ + (size_t)row * ISZ;
    bf16* olo = g_xlo + (size_t)which * ROWS * ISZ + (size_t)row * ISZ;

    int tid  = threadIdx.x;
    int lane = tid & 31, wid = tid >> 5;

    float vals[4];
    float s = 0.f;
#pragma unroll
    for (int i = 0; i < 4; i++) { vals[i] = x[tid + i * 256]; s += vals[i]; }
#pragma unroll
    for (int o = 16; o > 0; o >>= 1) s += __shfl_xor_sync(0xffffffffu, s, o);
    if (lane == 0) sbuf[wid] = s;
    __syncthreads();
    if (tid < 32) {
        float t = (tid < 8) ? sbuf[tid] : 0.f;
#pragma unroll
        for (int o = 4; o > 0; o >>= 1) t += __shfl_xor_sync(0xffffffffu, t, o);
        if (tid == 0) sbuf[0] = t;
    }
    __syncthreads();
    float mu = sbuf[0] * (1.f / ISZ);
    __syncthreads();

    float sq = 0.f;
#pragma unroll
    for (int i = 0; i < 4; i++) { float d = vals[i] - mu; sq += d * d; }
#pragma unroll
    for (int o = 16; o > 0; o >>= 1) sq += __shfl_xor_sync(0xffffffffu, sq, o);
    if (lane == 0) sbuf[wid] = sq;
    __syncthreads();
    if (tid < 32) {
        float t = (tid < 8) ? sbuf[tid] : 0.f;
#pragma unroll
        for (int o = 4; o > 0; o >>= 1) t += __shfl_xor_sync(0xffffffffu, t, o);
        if (tid == 0) sbuf[0] = t;
    }
    __syncthreads();
    float rstd = rsqrtf(sbuf[0] * (1.f / ISZ) + 1e-5f);

#pragma unroll
    for (int i = 0; i < 4; i++) {
        int idx = tid + i * 256;
        float y = (vals[i] - mu) * rstd * g[idx] + beta[idx];
        bf16 hi = __float2bfloat16(y);
        ohi[idx] = hi;
        olo[idx] = __float2bfloat16(y - __bfloat162float(hi));
    }
}

// ---------------------------------------------------------------------------
// Weight transpose + split: W[K][N] fp32 -> Wt_hi/lo[N][K] bf16
// ---------------------------------------------------------------------------
__global__ __launch_bounds__(256) void wconv_kernel(
    const float* __restrict__ W0, const float* __restrict__ W1,
    const float* __restrict__ W2, const float* __restrict__ W3)
{
    __shared__ float tile[32][33];
    int mat = blockIdx.z;
    const float* W = (mat == 0 ? W0 : mat == 1 ? W1 : mat == 2 ? W2 : W3);
    bf16* oh = g_wth + (size_t)mat * ISZ * ISZ;
    bf16* ol = g_wtl + (size_t)mat * ISZ * ISZ;

    int nt = blockIdx.x * 32, kt = blockIdx.y * 32;
    int tx = threadIdx.x & 31, ty = threadIdx.x >> 5;   // 32 x 8

#pragma unroll
    for (int i = 0; i < 4; i++)
        tile[ty + i * 8][tx] = W[(size_t)(kt + ty + i * 8) * ISZ + nt + tx];
    __syncthreads();
#pragma unroll
    for (int i = 0; i < 4; i++) {
        int n = nt + ty + i * 8;
        float w = tile[tx][ty + i * 8];
        bf16 hi = __float2bfloat16(w);
        oh[(size_t)n * ISZ + kt + tx] = hi;
        ol[(size_t)n * ISZ + kt + tx] = __float2bfloat16(w - __bfloat162float(hi));
    }
}

// ---------------------------------------------------------------------------
// Tensor-core GEMM via mma.sync (split bf16, 3 terms), occupancy-tuned:
// K staged 32-wide (smem 80KB), launch_bounds(256,2) -> 2 CTAs/SM.
// blockIdx.z selects one of up to 3 operand sets (fused QKV launch).
// ---------------------------------------------------------------------------
#define GM 4096
#define GN 1024
#define GK 1024
#define KST 32
#define NST (GK / KST)          // 32 stages
#define SK  40                  // smem row stride in bf16 (80 B)
#define PBY (128 * SK * 2)      // bytes per piece: 10240
#define STB (4 * PBY)           // per stage: 40960
#define GSMEM (2 * STB)         // 81920

__global__ __launch_bounds__(256, 2) void gemm_mma(
    const bf16* __restrict__ A0h, const bf16* __restrict__ A0l,
    const bf16* __restrict__ B0h, const bf16* __restrict__ B0l,
    const float* __restrict__ bias0, const float* __restrict__ mask0,
    float* __restrict__ C0,
    const bf16* __restrict__ A1h, const bf16* __restrict__ A1l,
    const bf16* __restrict__ B1h, const bf16* __restrict__ B1l,
    const float* __restrict__ bias1, const float* __restrict__ mask1,
    float* __restrict__ C1,
    const bf16* __restrict__ A2h, const bf16* __restrict__ A2l,
    const bf16* __restrict__ B2h, const bf16* __restrict__ B2l,
    const float* __restrict__ bias2, const float* __restrict__ mask2,
    float* __restrict__ C2)
{
    extern __shared__ __align__(128) char smc[];
    uint32_t sb = smem_u32(smc);

    int tid = threadIdx.x;
    int wid = tid >> 5, lane = tid & 31;
    int bn = blockIdx.x * 128, bm = blockIdx.y * 128;
    int z = blockIdx.z;
    int warp_m = (wid >> 2) * 64;
    int warp_n = (wid & 3) * 32;

    const bf16* Ahi = (z == 0) ? A0h : (z == 1) ? A1h : A2h;
    const bf16* Alo = (z == 0) ? A0l : (z == 1) ? A1l : A2l;
    const bf16* Bhi = (z == 0) ? B0h : (z == 1) ? B1h : B2h;
    const bf16* Blo = (z == 0) ? B0l : (z == 1) ? B1l : B2l;
    const float* bias = (z == 0) ? bias0 : (z == 1) ? bias1 : bias2;
    const float* mask = (z == 0) ? mask0 : (z == 1) ? mask1 : mask2;
    float* C = (z == 0) ? C0 : (z == 1) ? C1 : C2;

    const bf16* srcs[4] = {
        Ahi + (size_t)bm * GK, Alo + (size_t)bm * GK,
        Bhi + (size_t)bn * GK, Blo + (size_t)bn * GK };

    // per stage: 4 pieces x 128 rows x 2 chunks(16B)/thread (8 chunks total)
    auto load_stage = [&](int t, int s) {
        int k0 = t * KST;
        uint32_t dbase = sb + s * STB;
#pragma unroll
        for (int buf = 0; buf < 4; buf++) {
#pragma unroll
            for (int i = 0; i < 2; i++) {
                int chunk = tid + i * 256;          // 0..511
                int r = chunk >> 2, c = chunk & 3;  // row, 16B chunk
                const void* src = srcs[buf] + (size_t)r * GK + k0 + c * 8;
                uint32_t dst = dbase + buf * PBY + r * (SK * 2) + c * 16;
                cp_async16(dst, src);
            }
        }
    };

    float acc[4][4][4];
#pragma unroll
    for (int i = 0; i < 4; i++)
#pragma unroll
        for (int j = 0; j < 4; j++)
#pragma unroll
            for (int r = 0; r < 4; r++) acc[i][j][r] = 0.f;

    int a_row = lane & 15;
    int a_kh  = (lane >> 4) * 16;
    int b_row = lane & 7;
    int b_kh  = ((lane >> 3) & 1) * 16;

    load_stage(0, 0);
    cp_commit();

    for (int t = 0; t < NST; t++) {
        int s = t & 1;
        if (t + 1 < NST) { load_stage(t + 1, s ^ 1); cp_commit(); cp_wait1(); }
        else             { cp_wait0(); }
        __syncthreads();

        uint32_t st = sb + s * STB;
#pragma unroll
        for (int k16 = 0; k16 < 2; k16++) {
            uint32_t kb = k16 * 32;
            // B fragments first (16 regs), then A per-mt (8 regs live)
            uint32_t bh[4][2], bl[4][2];
#pragma unroll
            for (int nt = 0; nt < 4; nt++) {
                uint32_t rb = (warp_n + nt * 8 + b_row) * (SK * 2) + kb + b_kh;
                ldsm_x2(bh[nt][0], bh[nt][1], st + 2 * PBY + rb);
                ldsm_x2(bl[nt][0], bl[nt][1], st + 3 * PBY + rb);
            }
#pragma unroll
            for (int mt = 0; mt < 4; mt++) {
                uint32_t ra = (warp_m + mt * 16 + a_row) * (SK * 2) + kb + a_kh;
                uint32_t ah[4], al[4];
                ldsm_x4(ah[0], ah[1], ah[2], ah[3], st + ra);
                ldsm_x4(al[0], al[1], al[2], al[3], st + PBY + ra);
#pragma unroll
                for (int nt = 0; nt < 4; nt++) {
                    mma_bf16(acc[mt][nt], ah, bh[nt]);
                    mma_bf16(acc[mt][nt], ah, bl[nt]);
                    mma_bf16(acc[mt][nt], al, bh[nt]);
                }
            }
        }
        __syncthreads();
    }

#pragma unroll
    for (int mt = 0; mt < 4; mt++) {
        int r0 = bm + warp_m + mt * 16 + (lane >> 2);
        int r1 = r0 + 8;
        float mk0 = mask[r0], mk1 = mask[r1];
        float* c0 = C + (size_t)r0 * GN;
        float* c1 = C + (size_t)r1 * GN;
#pragma unroll
        for (int nt = 0; nt < 4; nt++) {
            int col = bn + warp_n + nt * 8 + (lane & 3) * 2;
            float2 o0, o1;
            o0.x = (acc[mt][nt][0] + bias[col + 0]) * mk0;
            o0.y = (acc[mt][nt][1] + bias[col + 1]) * mk0;
            o1.x = (acc[mt][nt][2] + bias[col + 0]) * mk1;
            o1.y = (acc[mt][nt][3] + bias[col + 1]) * mk1;
            *(float2*)(c0 + col) = o0;
            *(float2*)(c1 + col) = o1;
        }
    }
}

// ---------------------------------------------------------------------------
// Flash attention on tensor cores (fp16 mma.sync). Unchanged (proven).
// ---------------------------------------------------------------------------
#define AST 72   // smem row stride in halves (144 B)

__global__ __launch_bounds__(256) void attn_mma(
    const float* __restrict__ Qw, const float* __restrict__ Kw,
    const float* __restrict__ Vw)
{
    __shared__ __align__(16) __half asm_h[128 * AST * 2];  // 36864 B
    __half* Qh = asm_h;
    __half* Ql = asm_h + 128 * AST;
    __half* Ks = asm_h;
    __half* Vs = asm_h + 64 * AST;

    int tid = threadIdx.x;
    int wid = tid >> 5, lane = tid & 31;
    int qb = (int)(gridDim.x - 1 - blockIdx.x);
    int bh = blockIdx.y;
    int b = bh >> 4, h = bh & 15;

    size_t tokQ = (size_t)b * SEQ + qb * 128;
    int colBase = h * HDIM;

#pragma unroll
    for (int i = 0; i < 8; i++) {
        int p = tid + i * 256;
        int r = p >> 4, c4 = p & 15;
        float4 qv = *(const float4*)(Qw + (tokQ + r) * ISZ + colBase + c4 * 4);
        float y[4] = { qv.x * 0.125f, qv.y * 0.125f, qv.z * 0.125f, qv.w * 0.125f };
#pragma unroll
        for (int e = 0; e < 4; e++) {
            __half hi = __float2half_rn(y[e]);
            Qh[r * AST + c4 * 4 + e] = hi;
            Ql[r * AST + c4 * 4 + e] = __float2half_rn(y[e] - __half2float(hi));
        }
    }
    __syncthreads();

    uint32_t qfh[4][4], qfl[4][4];
    {
        uint32_t qb0 = smem_u32(Qh);
        uint32_t qb1 = smem_u32(Ql);
        int a_row = lane & 15;
        int a_kh  = (lane >> 4) * 16;
#pragma unroll
        for (int j = 0; j < 4; j++) {
            uint32_t off = (wid * 16 + a_row) * (AST * 2) + j * 32 + a_kh;
            ldsm_x4(qfh[j][0], qfh[j][1], qfh[j][2], qfh[j][3], qb0 + off);
            ldsm_x4(qfl[j][0], qfl[j][1], qfl[j][2], qfl[j][3], qb1 + off);
        }
    }

    float O[8][4];
#pragma unroll
    for (int nt = 0; nt < 8; nt++)
#pragma unroll
        for (int e = 0; e < 4; e++) O[nt][e] = 0.f;
    float mrow[2] = { -3e38f, -3e38f };
    float lrow[2] = { 0.f, 0.f };

    uint32_t ksb = smem_u32(Ks);
    uint32_t vsb = smem_u32(Vs);
    int b_row = lane & 7;
    int b_kh  = ((lane >> 3) & 1) * 16;

    int nkt = 2 * qb + 2;
    for (int kt = 0; kt < nkt; kt++) {
        __syncthreads();
        size_t tokK = (size_t)b * SEQ + kt * 64;
#pragma unroll
        for (int i = 0; i < 4; i++) {
            int p = tid + i * 256;
            int r = p >> 4, c4 = p & 15;
            float4 kv = *(const float4*)(Kw + (tokK + r) * ISZ + colBase + c4 * 4);
            *(uint32_t*)(Ks + r * AST + c4 * 4)     = h2pack(kv.x, kv.y);
            *(uint32_t*)(Ks + r * AST + c4 * 4 + 2) = h2pack(kv.z, kv.w);
            float4 vv = *(const float4*)(Vw + (tokK + r) * ISZ + colBase + c4 * 4);
            *(uint32_t*)(Vs + r * AST + c4 * 4)     = h2pack(vv.x, vv.y);
            *(uint32_t*)(Vs + r * AST + c4 * 4 + 2) = h2pack(vv.z, vv.w);
        }
        __syncthreads();

        float S[8][4];
#pragma unroll
        for (int nt = 0; nt < 8; nt++)
#pragma unroll
            for (int e = 0; e < 4; e++) S[nt][e] = 0.f;

#pragma unroll
        for (int j = 0; j < 4; j++) {
#pragma unroll
            for (int nt = 0; nt < 8; nt++) {
                uint32_t kf[2];
                ldsm_x2(kf[0], kf[1], ksb + (nt * 8 + b_row) * (AST * 2) + j * 32 + b_kh);
                mma_f16(S[nt], qfh[j], kf);
                mma_f16(S[nt], qfl[j], kf);
            }
        }

        if (kt >= 2 * qb) {
            int Rb = qb * 128 + wid * 16 + (lane >> 2);
#pragma unroll
            for (int nt = 0; nt < 8; nt++)
#pragma unroll
                for (int e = 0; e < 4; e++) {
                    int R = Rb + (e >> 1) * 8;
                    int C = kt * 64 + nt * 8 + 2 * (lane & 3) + (e & 1);
                    if (C > R) S[nt][e] = -3e38f;
                }
        }

#pragma unroll
        for (int hh = 0; hh < 2; hh++) {
            float mx = -3e38f;
#pragma unroll
            for (int nt = 0; nt < 8; nt++) {
                mx = fmaxf(mx, S[nt][2 * hh]);
                mx = fmaxf(mx, S[nt][2 * hh + 1]);
            }
            mx = fmaxf(mx, __shfl_xor_sync(0xffffffffu, mx, 1));
            mx = fmaxf(mx, __shfl_xor_sync(0xffffffffu, mx, 2));

            float mnew = fmaxf(mrow[hh], mx);
            float corr = __expf(mrow[hh] - mnew);
            float ts = 0.f;
#pragma unroll
            for (int nt = 0; nt < 8; nt++) {
                float p0 = __expf(S[nt][2 * hh]     - mnew);
                float p1 = __expf(S[nt][2 * hh + 1] - mnew);
                S[nt][2 * hh]     = p0;
                S[nt][2 * hh + 1] = p1;
                ts += p0 + p1;
            }
            ts += __shfl_xor_sync(0xffffffffu, ts, 1);
            ts += __shfl_xor_sync(0xffffffffu, ts, 2);

            lrow[hh] = lrow[hh] * corr + ts;
            mrow[hh] = mnew;
#pragma unroll
            for (int nt = 0; nt < 8; nt++) {
                O[nt][2 * hh]     *= corr;
                O[nt][2 * hh + 1] *= corr;
            }
        }

#pragma unroll
        for (int j = 0; j < 4; j++) {
            uint32_t ph[4], pl[4];
#pragma unroll
            for (int r = 0; r < 4; r++) {
                int nt = 2 * j + (r >> 1);
                int e0 = (r & 1) * 2;
                float p0 = S[nt][e0], p1 = S[nt][e0 + 1];
                __half h0 = __float2half_rn(p0), h1 = __float2half_rn(p1);
                __half2 hp = __halves2half2(h0, h1);
                ph[r] = *(uint32_t*)&hp;
                pl[r] = h2pack(p0 - __half2float(h0), p1 - __half2float(h1));
            }
#pragma unroll
            for (int nt = 0; nt < 8; nt++) {
                uint32_t vf[2];
                ldsm_x2t(vf[0], vf[1], vsb + (j * 16 + (lane & 15)) * (AST * 2) + nt * 16);
                mma_f16(O[nt], ph, vf);
                mma_f16(O[nt], pl, vf);
            }
        }
    }

#pragma unroll
    for (int hh = 0; hh < 2; hh++) {
        float inv = 1.f / lrow[hh];
        size_t tok = tokQ + wid * 16 + (lane >> 2) + 8 * hh;
#pragma unroll
        for (int nt = 0; nt < 8; nt++) {
            int col = colBase + nt * 8 + 2 * (lane & 3);
            float y0 = O[nt][2 * hh] * inv;
            float y1 = O[nt][2 * hh + 1] * inv;
            bf16 h0 = __float2bfloat16(y0);
            bf16 h1 = __float2bfloat16(y1);
            __nv_bfloat162 hv = { h0, h1 };
            __nv_bfloat162 lv = { __float2bfloat16(y0 - __bfloat162float(h0)),
                                  __float2bfloat16(y1 - __bfloat162float(h1)) };
            *(__nv_bfloat162*)(g_aoh + tok * ISZ + col) = hv;
            *(__nv_bfloat162*)(g_aol + tok * ISZ + col) = lv;
        }
    }
}

// ---------------------------------------------------------------------------
// Launch
// ---------------------------------------------------------------------------
template <typename T> static T* symaddr(const void* sym) {
    void* p; cudaGetSymbolAddress(&p, sym); return (T*)p;
}

extern "C" void kernel_launch(void* const* d_in, const int* in_sizes, int n_in,
                              void* d_out, int out_size)
{
    const float* q       = (const float*)d_in[0];
    const float* k       = (const float*)d_in[1];
    const float* v       = (const float*)d_in[2];
    const float* q_mask  = (const float*)d_in[3];
    const float* kv_mask = (const float*)d_in[4];
    const float* ln_g    = (const float*)d_in[6];
    const float* ln_b    = (const float*)d_in[7];
    const float* Wq      = (const float*)d_in[8];
    const float* bq      = (const float*)d_in[9];
    const float* Wk      = (const float*)d_in[10];
    const float* bk      = (const float*)d_in[11];
    const float* Wv      = (const float*)d_in[12];
    const float* bv      = (const float*)d_in[13];
    const float* Wo      = (const float*)d_in[14];
    const float* bo      = (const float*)d_in[15];
    float* out = (float*)d_out;

    bf16*  xhi = symaddr<bf16>(g_xhi);
    bf16*  xlo = symaddr<bf16>(g_xlo);
    bf16*  wth = symaddr<bf16>(g_wth);
    bf16*  wtl = symaddr<bf16>(g_wtl);
    float* qw  = symaddr<float>(g_qw);
    float* kw  = symaddr<float>(g_kw);
    float* vw  = symaddr<float>(g_vw);
    bf16*  aoh = symaddr<bf16>(g_aoh);
    bf16*  aol = symaddr<bf16>(g_aol);

    const size_t T = (size_t)ROWS * ISZ;
    const size_t WSZ = (size_t)ISZ * ISZ;

    // 1) LayerNorm -> split bf16
    ln3_kernel<<<3 * ROWS, 256>>>(q, k, v, ln_g, ln_b);

    // 2) Weight transpose + split
    wconv_kernel<<<dim3(32, 32, 4), 256>>>(Wq, Wk, Wv, Wo);

    // 3) QKV projections: one fused launch (z = q,k,v)
    cudaFuncSetAttribute(gemm_mma,
                         cudaFuncAttributeMaxDynamicSharedMemorySize, GSMEM);
    dim3 qkvgrid(GN / 128, GM / 128, 3);
    gemm_mma<<<qkvgrid, 256, GSMEM>>>(
        xhi,         xlo,         wth,           wtl,           bq, q_mask,  qw,
        xhi + T,     xlo + T,     wth + WSZ,     wtl + WSZ,     bk, kv_mask, kw,
        xhi + 2 * T, xlo + 2 * T, wth + 2 * WSZ, wtl + 2 * WSZ, bv, kv_mask, vw);

    // 4) Flash attention on tensor cores -> split bf16
    dim3 agrid(SEQ / 128, BATCH * NHEAD);
    attn_mma<<<agrid, 256>>>(qw, kw, vw);

    // 5) Output projection straight into d_out
    dim3 ogrid(GN / 128, GM / 128, 1);
    gemm_mma<<<ogrid, 256, GSMEM>>>(
        aoh, aol, wth + 3 * WSZ, wtl + 3 * WSZ, bo, kv_mask, out,
        aoh, aol, wth + 3 * WSZ, wtl + 3 * WSZ, bo, kv_mask, out,
        aoh, aol, wth + 3 * WSZ, wtl + 3 * WSZ, bo, kv_mask, out);
}

// round 11
// speedup vs baseline: 1.0896x; 1.0896x over previous
#include <cuda_runtime.h>
#include <cuda_bf16.h>
#include <cuda_fp16.h>
#include <math.h>
#include <stdint.h>

// Problem constants
#define BATCH 2
#define SEQ   2048
#define ISZ   1024
#define NHEAD 16
#define HDIM  64
#define ROWS  (BATCH*SEQ)      // 4096

typedef __nv_bfloat16 bf16;

// ---------------------------------------------------------------------------
// Scratch (device globals: allocation-free per harness rules)
// ---------------------------------------------------------------------------
__device__ bf16  g_xhi[(size_t)3*ROWS*ISZ];   // LN outputs hi (q,k,v)
__device__ bf16  g_xlo[(size_t)3*ROWS*ISZ];   // LN outputs lo
__device__ bf16  g_wth[(size_t)4*ISZ*ISZ];    // W^T hi (Wq,Wk,Wv,Wo)
__device__ bf16  g_wtl[(size_t)4*ISZ*ISZ];    // W^T lo
__device__ float g_qw[(size_t)ROWS*ISZ];
__device__ float g_kw[(size_t)ROWS*ISZ];
__device__ float g_vw[(size_t)ROWS*ISZ];
__device__ bf16  g_aoh[(size_t)ROWS*ISZ];     // attention out hi
__device__ bf16  g_aol[(size_t)ROWS*ISZ];     // attention out lo

// ---------------------------------------------------------------------------
// PTX helpers (Ampere-compatible: cp.async, ldmatrix, mma.sync)
// ---------------------------------------------------------------------------
__device__ __forceinline__ uint32_t smem_u32(const void* p) {
    return (uint32_t)__cvta_generic_to_shared(p);
}
__device__ __forceinline__ void cp_async16(uint32_t dst, const void* src) {
    asm volatile("cp.async.cg.shared.global [%0], [%1], 16;\n" :: "r"(dst), "l"(src));
}
__device__ __forceinline__ void cp_commit() {
    asm volatile("cp.async.commit_group;\n");
}
__device__ __forceinline__ void cp_wait1() {
    asm volatile("cp.async.wait_group 1;\n");
}
__device__ __forceinline__ void cp_wait0() {
    asm volatile("cp.async.wait_group 0;\n");
}
__device__ __forceinline__ void ldsm_x4(uint32_t& r0, uint32_t& r1,
                                        uint32_t& r2, uint32_t& r3, uint32_t a) {
    asm volatile("ldmatrix.sync.aligned.m8n8.x4.shared.b16 {%0,%1,%2,%3}, [%4];"
                 : "=r"(r0), "=r"(r1), "=r"(r2), "=r"(r3) : "r"(a));
}
__device__ __forceinline__ void ldsm_x2(uint32_t& r0, uint32_t& r1, uint32_t a) {
    asm volatile("ldmatrix.sync.aligned.m8n8.x2.shared.b16 {%0,%1}, [%2];"
                 : "=r"(r0), "=r"(r1) : "r"(a));
}
__device__ __forceinline__ void ldsm_x2t(uint32_t& r0, uint32_t& r1, uint32_t a) {
    asm volatile("ldmatrix.sync.aligned.m8n8.x2.trans.shared.b16 {%0,%1}, [%2];"
                 : "=r"(r0), "=r"(r1) : "r"(a));
}
__device__ __forceinline__ void mma_bf16(float* d, const uint32_t* a, const uint32_t* b) {
    asm volatile("mma.sync.aligned.m16n8k16.row.col.f32.bf16.bf16.f32 "
                 "{%0,%1,%2,%3}, {%4,%5,%6,%7}, {%8,%9}, {%0,%1,%2,%3};"
                 : "+f"(d[0]), "+f"(d[1]), "+f"(d[2]), "+f"(d[3])
                 : "r"(a[0]), "r"(a[1]), "r"(a[2]), "r"(a[3]), "r"(b[0]), "r"(b[1]));
}
__device__ __forceinline__ void mma_f16(float* d, const uint32_t* a, const uint32_t* b) {
    asm volatile("mma.sync.aligned.m16n8k16.row.col.f32.f16.f16.f32 "
                 "{%0,%1,%2,%3}, {%4,%5,%6,%7}, {%8,%9}, {%0,%1,%2,%3};"
                 : "+f"(d[0]), "+f"(d[1]), "+f"(d[2]), "+f"(d[3])
                 : "r"(a[0]), "r"(a[1]), "r"(a[2]), "r"(a[3]), "r"(b[0]), "r"(b[1]));
}
__device__ __forceinline__ uint32_t h2pack(float a, float b) {
    __half2 h = __floats2half2_rn(a, b);
    return *(uint32_t*)&h;
}

// ---------------------------------------------------------------------------
// LayerNorm: one block per row; writes split-bf16 (hi, lo)
// ---------------------------------------------------------------------------
__global__ __launch_bounds__(256) void ln3_kernel(
    const float* __restrict__ q, const float* __restrict__ k,
    const float* __restrict__ v, const float* __restrict__ g,
    const float* __restrict__ beta)
{
    __shared__ float sbuf[8];
    int which = blockIdx.x >> 12;
    int row   = blockIdx.x & 4095;
    const float* x =
        (which == 0 ? q : which == 1 ? k : v) + (size_t)row * ISZ;
    bf16* ohi = g_xhi + (size_t)which * ROWS * ISZ + (size_t)row * ISZ;
    bf16* olo = g_xlo + (size_t)which * ROWS * ISZ + (size_t)row * ISZ;

    int tid  = threadIdx.x;
    int lane = tid & 31, wid = tid >> 5;

    float vals[4];
    float s = 0.f;
#pragma unroll
    for (int i = 0; i < 4; i++) { vals[i] = x[tid + i * 256]; s += vals[i]; }
#pragma unroll
    for (int o = 16; o > 0; o >>= 1) s += __shfl_xor_sync(0xffffffffu, s, o);
    if (lane == 0) sbuf[wid] = s;
    __syncthreads();
    if (tid < 32) {
        float t = (tid < 8) ? sbuf[tid] : 0.f;
#pragma unroll
        for (int o = 4; o > 0; o >>= 1) t += __shfl_xor_sync(0xffffffffu, t, o);
        if (tid == 0) sbuf[0] = t;
    }
    __syncthreads();
    float mu = sbuf[0] * (1.f / ISZ);
    __syncthreads();

    float sq = 0.f;
#pragma unroll
    for (int i = 0; i < 4; i++) { float d = vals[i] - mu; sq += d * d; }
#pragma unroll
    for (int o = 16; o > 0; o >>= 1) sq += __shfl_xor_sync(0xffffffffu, sq, o);
    if (lane == 0) sbuf[wid] = sq;
    __syncthreads();
    if (tid < 32) {
        float t = (tid < 8) ? sbuf[tid] : 0.f;
#pragma unroll
        for (int o = 4; o > 0; o >>= 1) t += __shfl_xor_sync(0xffffffffu, t, o);
        if (tid == 0) sbuf[0] = t;
    }
    __syncthreads();
    float rstd = rsqrtf(sbuf[0] * (1.f / ISZ) + 1e-5f);

#pragma unroll
    for (int i = 0; i < 4; i++) {
        int idx = tid + i * 256;
        float y = (vals[i] - mu) * rstd * g[idx] + beta[idx];
        bf16 hi = __float2bfloat16(y);
        ohi[idx] = hi;
        olo[idx] = __float2bfloat16(y - __bfloat162float(hi));
    }
}

// ---------------------------------------------------------------------------
// Weight transpose + split: W[K][N] fp32 -> Wt_hi/lo[N][K] bf16
// ---------------------------------------------------------------------------
__global__ __launch_bounds__(256) void wconv_kernel(
    const float* __restrict__ W0, const float* __restrict__ W1,
    const float* __restrict__ W2, const float* __restrict__ W3)
{
    __shared__ float tile[32][33];
    int mat = blockIdx.z;
    const float* W = (mat == 0 ? W0 : mat == 1 ? W1 : mat == 2 ? W2 : W3);
    bf16* oh = g_wth + (size_t)mat * ISZ * ISZ;
    bf16* ol = g_wtl + (size_t)mat * ISZ * ISZ;

    int nt = blockIdx.x * 32, kt = blockIdx.y * 32;
    int tx = threadIdx.x & 31, ty = threadIdx.x >> 5;   // 32 x 8

#pragma unroll
    for (int i = 0; i < 4; i++)
        tile[ty + i * 8][tx] = W[(size_t)(kt + ty + i * 8) * ISZ + nt + tx];
    __syncthreads();
#pragma unroll
    for (int i = 0; i < 4; i++) {
        int n = nt + ty + i * 8;
        float w = tile[tx][ty + i * 8];
        bf16 hi = __float2bfloat16(w);
        oh[(size_t)n * ISZ + kt + tx] = hi;
        ol[(size_t)n * ISZ + kt + tx] = __float2bfloat16(w - __bfloat162float(hi));
    }
}

// ---------------------------------------------------------------------------
// Tensor-core GEMM via mma.sync (split bf16, 3 terms) — round-6 proven config
// ---------------------------------------------------------------------------
#define GM 4096
#define GN 1024
#define GK 1024
#define KST 64
#define NST (GK / KST)          // 16 stages
#define SK  72                  // smem stride in bf16
#define PBY (128 * SK * 2)      // bytes per piece: 18432
#define STB (4 * PBY)           // per stage: 73728
#define GSMEM (2 * STB)         // 147456

__global__ __launch_bounds__(256, 1) void gemm_mma(
    const bf16* __restrict__ Ahi, const bf16* __restrict__ Alo,
    const bf16* __restrict__ Bhi, const bf16* __restrict__ Blo,
    const float* __restrict__ bias, const float* __restrict__ mask,
    float* __restrict__ C)
{
    extern __shared__ __align__(128) char smc[];
    uint32_t sb = smem_u32(smc);

    int tid = threadIdx.x;
    int wid = tid >> 5, lane = tid & 31;
    int bn = blockIdx.x * 128, bm = blockIdx.y * 128;
    int warp_m = (wid >> 2) * 64;
    int warp_n = (wid & 3) * 32;

    const bf16* srcs[4] = {
        Ahi + (size_t)bm * GK, Alo + (size_t)bm * GK,
        Bhi + (size_t)bn * GK, Blo + (size_t)bn * GK };

    auto load_stage = [&](int t, int s) {
        int k0 = t * KST;
        uint32_t dbase = sb + s * STB;
#pragma unroll
        for (int buf = 0; buf < 4; buf++) {
#pragma unroll
            for (int i = 0; i < 4; i++) {
                int chunk = tid + i * 256;
                int r = chunk >> 3, c = chunk & 7;
                const void* src = srcs[buf] + (size_t)r * GK + k0 + c * 8;
                uint32_t dst = dbase + buf * PBY + r * (SK * 2) + c * 16;
                cp_async16(dst, src);
            }
        }
    };

    float acc[4][4][4];
#pragma unroll
    for (int i = 0; i < 4; i++)
#pragma unroll
        for (int j = 0; j < 4; j++)
#pragma unroll
            for (int r = 0; r < 4; r++) acc[i][j][r] = 0.f;

    int a_row = lane & 15;
    int a_kh  = (lane >> 4) * 16;
    int b_row = lane & 7;
    int b_kh  = ((lane >> 3) & 1) * 16;

    load_stage(0, 0);
    cp_commit();

    for (int t = 0; t < NST; t++) {
        int s = t & 1;
        if (t + 1 < NST) { load_stage(t + 1, s ^ 1); cp_commit(); cp_wait1(); }
        else             { cp_wait0(); }
        __syncthreads();

        uint32_t st = sb + s * STB;
#pragma unroll
        for (int k16 = 0; k16 < 4; k16++) {
            uint32_t kb = k16 * 32;
            uint32_t ah[4][4], al[4][4], bh[4][2], bl[4][2];
#pragma unroll
            for (int mt = 0; mt < 4; mt++) {
                uint32_t ra = (warp_m + mt * 16 + a_row) * (SK * 2) + kb + a_kh;
                ldsm_x4(ah[mt][0], ah[mt][1], ah[mt][2], ah[mt][3], st + ra);
                ldsm_x4(al[mt][0], al[mt][1], al[mt][2], al[mt][3], st + PBY + ra);
            }
#pragma unroll
            for (int nt = 0; nt < 4; nt++) {
                uint32_t rb = (warp_n + nt * 8 + b_row) * (SK * 2) + kb + b_kh;
                ldsm_x2(bh[nt][0], bh[nt][1], st + 2 * PBY + rb);
                ldsm_x2(bl[nt][0], bl[nt][1], st + 3 * PBY + rb);
            }
#pragma unroll
            for (int mt = 0; mt < 4; mt++)
#pragma unroll
                for (int nt = 0; nt < 4; nt++) {
                    mma_bf16(acc[mt][nt], ah[mt], bh[nt]);
                    mma_bf16(acc[mt][nt], ah[mt], bl[nt]);
                    mma_bf16(acc[mt][nt], al[mt], bh[nt]);
                }
        }
        __syncthreads();
    }

#pragma unroll
    for (int mt = 0; mt < 4; mt++) {
        int r0 = bm + warp_m + mt * 16 + (lane >> 2);
        int r1 = r0 + 8;
        float mk0 = mask[r0], mk1 = mask[r1];
        float* c0 = C + (size_t)r0 * GN;
        float* c1 = C + (size_t)r1 * GN;
#pragma unroll
        for (int nt = 0; nt < 4; nt++) {
            int col = bn + warp_n + nt * 8 + (lane & 3) * 2;
            float2 o0, o1;
            o0.x = (acc[mt][nt][0] + bias[col + 0]) * mk0;
            o0.y = (acc[mt][nt][1] + bias[col + 1]) * mk0;
            o1.x = (acc[mt][nt][2] + bias[col + 0]) * mk1;
            o1.y = (acc[mt][nt][3] + bias[col + 1]) * mk1;
            *(float2*)(c0 + col) = o0;
            *(float2*)(c1 + col) = o1;
        }
    }
}

// ---------------------------------------------------------------------------
// Flash attention on tensor cores (fp16 mma.sync), occupancy-tuned:
// Q hi/lo kept in PERSISTENT smem (not registers) -> ~32 fewer live regs ->
// launch_bounds(256,2) = 2 CTAs/SM. Q frags re-loaded via ldmatrix per tile.
// Dynamic smem: Qh+Ql (36864B) + Ks+Vs (18432B) = 55296B/CTA.
// ---------------------------------------------------------------------------
#define AST 72   // smem row stride in halves (144 B)
#define ATTN_SMEM ((2 * 128 * AST + 2 * 64 * AST) * 2)   // 55296 bytes

__global__ __launch_bounds__(256, 2) void attn_mma(
    const float* __restrict__ Qw, const float* __restrict__ Kw,
    const float* __restrict__ Vw)
{
    extern __shared__ __align__(16) __half ash[];
    __half* Qh = ash;                         // [128][AST] persistent
    __half* Ql = ash + 128 * AST;             // [128][AST] persistent
    __half* Ks = ash + 2 * 128 * AST;         // [64][AST]
    __half* Vs = ash + 2 * 128 * AST + 64 * AST;

    int tid = threadIdx.x;
    int wid = tid >> 5, lane = tid & 31;
    int qb = (int)(gridDim.x - 1 - blockIdx.x);   // heavy blocks first
    int bh = blockIdx.y;
    int b = bh >> 4, h = bh & 15;

    size_t tokQ = (size_t)b * SEQ + qb * 128;
    int colBase = h * HDIM;

    // ---- stage Q (scaled by 0.125, split fp16 hi/lo) ----
#pragma unroll
    for (int i = 0; i < 8; i++) {
        int p = tid + i * 256;           // 0..2047 = 128 rows x 16 float4
        int r = p >> 4, c4 = p & 15;
        float4 qv = *(const float4*)(Qw + (tokQ + r) * ISZ + colBase + c4 * 4);
        float y[4] = { qv.x * 0.125f, qv.y * 0.125f, qv.z * 0.125f, qv.w * 0.125f };
#pragma unroll
        for (int e = 0; e < 4; e++) {
            __half hi = __float2half_rn(y[e]);
            Qh[r * AST + c4 * 4 + e] = hi;
            Ql[r * AST + c4 * 4 + e] = __float2half_rn(y[e] - __half2float(hi));
        }
    }
    __syncthreads();

    float O[8][4];
#pragma unroll
    for (int nt = 0; nt < 8; nt++)
#pragma unroll
        for (int e = 0; e < 4; e++) O[nt][e] = 0.f;
    float mrow[2] = { -3e38f, -3e38f };
    float lrow[2] = { 0.f, 0.f };

    uint32_t qb0 = smem_u32(Qh);
    uint32_t qb1 = smem_u32(Ql);
    uint32_t ksb = smem_u32(Ks);
    uint32_t vsb = smem_u32(Vs);
    int a_row = lane & 15;
    int a_kh  = (lane >> 4) * 16;
    int b_row = lane & 7;
    int b_kh  = ((lane >> 3) & 1) * 16;

    int nkt = 2 * qb + 2;
    for (int kt = 0; kt < nkt; kt++) {
        if (kt > 0) __syncthreads();    // prior tile fully consumed
        size_t tokK = (size_t)b * SEQ + kt * 64;
#pragma unroll
        for (int i = 0; i < 4; i++) {
            int p = tid + i * 256;       // 0..1023
            int r = p >> 4, c4 = p & 15;
            float4 kv = *(const float4*)(Kw + (tokK + r) * ISZ + colBase + c4 * 4);
            *(uint32_t*)(Ks + r * AST + c4 * 4)     = h2pack(kv.x, kv.y);
            *(uint32_t*)(Ks + r * AST + c4 * 4 + 2) = h2pack(kv.z, kv.w);
            float4 vv = *(const float4*)(Vw + (tokK + r) * ISZ + colBase + c4 * 4);
            *(uint32_t*)(Vs + r * AST + c4 * 4)     = h2pack(vv.x, vv.y);
            *(uint32_t*)(Vs + r * AST + c4 * 4 + 2) = h2pack(vv.z, vv.w);
        }
        __syncthreads();

        // ---- S = (Qhi+Qlo) @ K^T ----
        float S[8][4];
#pragma unroll
        for (int nt = 0; nt < 8; nt++)
#pragma unroll
            for (int e = 0; e < 4; e++) S[nt][e] = 0.f;

#pragma unroll
        for (int j = 0; j < 4; j++) {
            uint32_t qoff = (wid * 16 + a_row) * (AST * 2) + j * 32 + a_kh;
            uint32_t qfh[4], qfl[4];
            ldsm_x4(qfh[0], qfh[1], qfh[2], qfh[3], qb0 + qoff);
            ldsm_x4(qfl[0], qfl[1], qfl[2], qfl[3], qb1 + qoff);
#pragma unroll
            for (int nt = 0; nt < 8; nt++) {
                uint32_t kf[2];
                ldsm_x2(kf[0], kf[1], ksb + (nt * 8 + b_row) * (AST * 2) + j * 32 + b_kh);
                mma_f16(S[nt], qfh, kf);
                mma_f16(S[nt], qfl, kf);
            }
        }

        // ---- causal mask (diagonal tiles only) ----
        if (kt >= 2 * qb) {
            int Rb = qb * 128 + wid * 16 + (lane >> 2);
#pragma unroll
            for (int nt = 0; nt < 8; nt++)
#pragma unroll
                for (int e = 0; e < 4; e++) {
                    int R = Rb + (e >> 1) * 8;
                    int C = kt * 64 + nt * 8 + 2 * (lane & 3) + (e & 1);
                    if (C > R) S[nt][e] = -3e38f;
                }
        }

        // ---- online softmax ----
#pragma unroll
        for (int hh = 0; hh < 2; hh++) {
            float mx = -3e38f;
#pragma unroll
            for (int nt = 0; nt < 8; nt++) {
                mx = fmaxf(mx, S[nt][2 * hh]);
                mx = fmaxf(mx, S[nt][2 * hh + 1]);
            }
            mx = fmaxf(mx, __shfl_xor_sync(0xffffffffu, mx, 1));
            mx = fmaxf(mx, __shfl_xor_sync(0xffffffffu, mx, 2));

            float mnew = fmaxf(mrow[hh], mx);
            float corr = __expf(mrow[hh] - mnew);
            float ts = 0.f;
#pragma unroll
            for (int nt = 0; nt < 8; nt++) {
                float p0 = __expf(S[nt][2 * hh]     - mnew);
                float p1 = __expf(S[nt][2 * hh + 1] - mnew);
                S[nt][2 * hh]     = p0;
                S[nt][2 * hh + 1] = p1;
                ts += p0 + p1;
            }
            ts += __shfl_xor_sync(0xffffffffu, ts, 1);
            ts += __shfl_xor_sync(0xffffffffu, ts, 2);

            lrow[hh] = lrow[hh] * corr + ts;
            mrow[hh] = mnew;
#pragma unroll
            for (int nt = 0; nt < 8; nt++) {
                O[nt][2 * hh]     *= corr;
                O[nt][2 * hh + 1] *= corr;
            }
        }

        // ---- O += (Phi+Plo) @ V ----
#pragma unroll
        for (int j = 0; j < 4; j++) {
            uint32_t ph[4], pl[4];
#pragma unroll
            for (int r = 0; r < 4; r++) {
                int nt = 2 * j + (r >> 1);
                int e0 = (r & 1) * 2;
                float p0 = S[nt][e0], p1 = S[nt][e0 + 1];
                __half h0 = __float2half_rn(p0), h1 = __float2half_rn(p1);
                __half2 hp = __halves2half2(h0, h1);
                ph[r] = *(uint32_t*)&hp;
                pl[r] = h2pack(p0 - __half2float(h0), p1 - __half2float(h1));
            }
#pragma unroll
            for (int nt = 0; nt < 8; nt++) {
                uint32_t vf[2];
                ldsm_x2t(vf[0], vf[1], vsb + (j * 16 + (lane & 15)) * (AST * 2) + nt * 16);
                mma_f16(O[nt], ph, vf);
                mma_f16(O[nt], pl, vf);
            }
        }
    }

    // ---- epilogue: normalize, split bf16 hi/lo for the Wo GEMM ----
#pragma unroll
    for (int hh = 0; hh < 2; hh++) {
        float inv = 1.f / lrow[hh];
        size_t tok = tokQ + wid * 16 + (lane >> 2) + 8 * hh;
#pragma unroll
        for (int nt = 0; nt < 8; nt++) {
            int col = colBase + nt * 8 + 2 * (lane & 3);
            float y0 = O[nt][2 * hh] * inv;
            float y1 = O[nt][2 * hh + 1] * inv;
            bf16 h0 = __float2bfloat16(y0);
            bf16 h1 = __float2bfloat16(y1);
            __nv_bfloat162 hv = { h0, h1 };
            __nv_bfloat162 lv = { __float2bfloat16(y0 - __bfloat162float(h0)),
                                  __float2bfloat16(y1 - __bfloat162float(h1)) };
            *(__nv_bfloat162*)(g_aoh + tok * ISZ + col) = hv;
            *(__nv_bfloat162*)(g_aol + tok * ISZ + col) = lv;
        }
    }
}

// ---------------------------------------------------------------------------
// Launch
// ---------------------------------------------------------------------------
template <typename T> static T* symaddr(const void* sym) {
    void* p; cudaGetSymbolAddress(&p, sym); return (T*)p;
}

extern "C" void kernel_launch(void* const* d_in, const int* in_sizes, int n_in,
                              void* d_out, int out_size)
{
    const float* q       = (const float*)d_in[0];
    const float* k       = (const float*)d_in[1];
    const float* v       = (const float*)d_in[2];
    const float* q_mask  = (const float*)d_in[3];
    const float* kv_mask = (const float*)d_in[4];
    const float* ln_g    = (const float*)d_in[6];
    const float* ln_b    = (const float*)d_in[7];
    const float* Wq      = (const float*)d_in[8];
    const float* bq      = (const float*)d_in[9];
    const float* Wk      = (const float*)d_in[10];
    const float* bk      = (const float*)d_in[11];
    const float* Wv      = (const float*)d_in[12];
    const float* bv      = (const float*)d_in[13];
    const float* Wo      = (const float*)d_in[14];
    const float* bo      = (const float*)d_in[15];
    float* out = (float*)d_out;

    bf16*  xhi = symaddr<bf16>(g_xhi);
    bf16*  xlo = symaddr<bf16>(g_xlo);
    bf16*  wth = symaddr<bf16>(g_wth);
    bf16*  wtl = symaddr<bf16>(g_wtl);
    float* qw  = symaddr<float>(g_qw);
    float* kw  = symaddr<float>(g_kw);
    float* vw  = symaddr<float>(g_vw);
    bf16*  aoh = symaddr<bf16>(g_aoh);
    bf16*  aol = symaddr<bf16>(g_aol);

    const size_t T = (size_t)ROWS * ISZ;
    const size_t WSZ = (size_t)ISZ * ISZ;

    // 1) LayerNorm -> split bf16
    ln3_kernel<<<3 * ROWS, 256>>>(q, k, v, ln_g, ln_b);

    // 2) Weight transpose + split
    wconv_kernel<<<dim3(32, 32, 4), 256>>>(Wq, Wk, Wv, Wo);

    // 3) QKV projections (mma.sync)
    cudaFuncSetAttribute(gemm_mma,
                         cudaFuncAttributeMaxDynamicSharedMemorySize, GSMEM);
    dim3 ggrid(GN / 128, GM / 128);
    gemm_mma<<<ggrid, 256, GSMEM>>>(xhi,         xlo,         wth,           wtl,           bq, q_mask,  qw);
    gemm_mma<<<ggrid, 256, GSMEM>>>(xhi + T,     xlo + T,     wth + WSZ,     wtl + WSZ,     bk, kv_mask, kw);
    gemm_mma<<<ggrid, 256, GSMEM>>>(xhi + 2 * T, xlo + 2 * T, wth + 2 * WSZ, wtl + 2 * WSZ, bv, kv_mask, vw);

    // 4) Flash attention on tensor cores -> split bf16 (2 CTAs/SM)
    cudaFuncSetAttribute(attn_mma,
                         cudaFuncAttributeMaxDynamicSharedMemorySize, ATTN_SMEM);
    dim3 agrid(SEQ / 128, BATCH * NHEAD);
    attn_mma<<<agrid, 256, ATTN_SMEM>>>(qw, kw, vw);

    // 5) Output projection straight into d_out
    gemm_mma<<<ggrid, 256, GSMEM>>>(aoh, aol, wth + 3 * WSZ, wtl + 3 * WSZ, bo, kv_mask, out);
}

// round 12
// speedup vs baseline: 1.3026x; 1.1955x over previous
#include <cuda_runtime.h>
#include <cuda_bf16.h>
#include <cuda_fp16.h>
#include <math.h>
#include <stdint.h>

// Problem constants
#define BATCH 2
#define SEQ   2048
#define ISZ   1024
#define NHEAD 16
#define HDIM  64
#define ROWS  (BATCH*SEQ)      // 4096

// ---------------------------------------------------------------------------
// Scratch (device globals: allocation-free per harness rules)
// ---------------------------------------------------------------------------
__device__ __half g_xhi[(size_t)3*ROWS*ISZ];   // LN outputs hi (q,k,v)
__device__ __half g_xlo[(size_t)3*ROWS*ISZ];   // LN outputs lo
__device__ __half g_wth[(size_t)4*ISZ*ISZ];    // W^T fp16 (Wq,Wk,Wv,Wo)
__device__ float  g_qw[(size_t)ROWS*ISZ];
__device__ float  g_kw[(size_t)ROWS*ISZ];
__device__ float  g_vw[(size_t)ROWS*ISZ];
__device__ __half g_aoh[(size_t)ROWS*ISZ];     // attention out hi
__device__ __half g_aol[(size_t)ROWS*ISZ];     // attention out lo

// ---------------------------------------------------------------------------
// PTX helpers (Ampere-compatible: cp.async, ldmatrix, mma.sync)
// ---------------------------------------------------------------------------
__device__ __forceinline__ uint32_t smem_u32(const void* p) {
    return (uint32_t)__cvta_generic_to_shared(p);
}
__device__ __forceinline__ void cp_async16(uint32_t dst, const void* src) {
    asm volatile("cp.async.cg.shared.global [%0], [%1], 16;\n" :: "r"(dst), "l"(src));
}
__device__ __forceinline__ void cp_commit() {
    asm volatile("cp.async.commit_group;\n");
}
__device__ __forceinline__ void cp_wait1() {
    asm volatile("cp.async.wait_group 1;\n");
}
__device__ __forceinline__ void cp_wait0() {
    asm volatile("cp.async.wait_group 0;\n");
}
__device__ __forceinline__ void ldsm_x4(uint32_t& r0, uint32_t& r1,
                                        uint32_t& r2, uint32_t& r3, uint32_t a) {
    asm volatile("ldmatrix.sync.aligned.m8n8.x4.shared.b16 {%0,%1,%2,%3}, [%4];"
                 : "=r"(r0), "=r"(r1), "=r"(r2), "=r"(r3) : "r"(a));
}
__device__ __forceinline__ void ldsm_x2(uint32_t& r0, uint32_t& r1, uint32_t a) {
    asm volatile("ldmatrix.sync.aligned.m8n8.x2.shared.b16 {%0,%1}, [%2];"
                 : "=r"(r0), "=r"(r1) : "r"(a));
}
__device__ __forceinline__ void ldsm_x2t(uint32_t& r0, uint32_t& r1, uint32_t a) {
    asm volatile("ldmatrix.sync.aligned.m8n8.x2.trans.shared.b16 {%0,%1}, [%2];"
                 : "=r"(r0), "=r"(r1) : "r"(a));
}
__device__ __forceinline__ void mma_f16(float* d, const uint32_t* a, const uint32_t* b) {
    asm volatile("mma.sync.aligned.m16n8k16.row.col.f32.f16.f16.f32 "
                 "{%0,%1,%2,%3}, {%4,%5,%6,%7}, {%8,%9}, {%0,%1,%2,%3};"
                 : "+f"(d[0]), "+f"(d[1]), "+f"(d[2]), "+f"(d[3])
                 : "r"(a[0]), "r"(a[1]), "r"(a[2]), "r"(a[3]), "r"(b[0]), "r"(b[1]));
}
__device__ __forceinline__ uint32_t h2pack(float a, float b) {
    __half2 h = __floats2half2_rn(a, b);
    return *(uint32_t*)&h;
}

// ---------------------------------------------------------------------------
// LayerNorm: one block per row; writes split-fp16 (hi, lo)
// ---------------------------------------------------------------------------
__global__ __launch_bounds__(256) void ln3_kernel(
    const float* __restrict__ q, const float* __restrict__ k,
    const float* __restrict__ v, const float* __restrict__ g,
    const float* __restrict__ beta)
{
    __shared__ float sbuf[8];
    int which = blockIdx.x >> 12;
    int row   = blockIdx.x & 4095;
    const float* x =
        (which == 0 ? q : which == 1 ? k : v) + (size_t)row * ISZ;
    __half* ohi = g_xhi + (size_t)which * ROWS * ISZ + (size_t)row * ISZ;
    __half* olo = g_xlo + (size_t)which * ROWS * ISZ + (size_t)row * ISZ;

    int tid  = threadIdx.x;
    int lane = tid & 31, wid = tid >> 5;

    float vals[4];
    float s = 0.f;
#pragma unroll
    for (int i = 0; i < 4; i++) { vals[i] = x[tid + i * 256]; s += vals[i]; }
#pragma unroll
    for (int o = 16; o > 0; o >>= 1) s += __shfl_xor_sync(0xffffffffu, s, o);
    if (lane == 0) sbuf[wid] = s;
    __syncthreads();
    if (tid < 32) {
        float t = (tid < 8) ? sbuf[tid] : 0.f;
#pragma unroll
        for (int o = 4; o > 0; o >>= 1) t += __shfl_xor_sync(0xffffffffu, t, o);
        if (tid == 0) sbuf[0] = t;
    }
    __syncthreads();
    float mu = sbuf[0] * (1.f / ISZ);
    __syncthreads();

    float sq = 0.f;
#pragma unroll
    for (int i = 0; i < 4; i++) { float d = vals[i] - mu; sq += d * d; }
#pragma unroll
    for (int o = 16; o > 0; o >>= 1) sq += __shfl_xor_sync(0xffffffffu, sq, o);
    if (lane == 0) sbuf[wid] = sq;
    __syncthreads();
    if (tid < 32) {
        float t = (tid < 8) ? sbuf[tid] : 0.f;
#pragma unroll
        for (int o = 4; o > 0; o >>= 1) t += __shfl_xor_sync(0xffffffffu, t, o);
        if (tid == 0) sbuf[0] = t;
    }
    __syncthreads();
    float rstd = rsqrtf(sbuf[0] * (1.f / ISZ) + 1e-5f);

#pragma unroll
    for (int i = 0; i < 4; i++) {
        int idx = tid + i * 256;
        float y = (vals[i] - mu) * rstd * g[idx] + beta[idx];
        __half hi = __float2half_rn(y);
        ohi[idx] = hi;
        olo[idx] = __float2half_rn(y - __half2float(hi));
    }
}

// ---------------------------------------------------------------------------
// Weight transpose: W[K][N] fp32 -> Wt[N][K] fp16 (single precision level)
// ---------------------------------------------------------------------------
__global__ __launch_bounds__(256) void wconv_kernel(
    const float* __restrict__ W0, const float* __restrict__ W1,
    const float* __restrict__ W2, const float* __restrict__ W3)
{
    __shared__ float tile[32][33];
    int mat = blockIdx.z;
    const float* W = (mat == 0 ? W0 : mat == 1 ? W1 : mat == 2 ? W2 : W3);
    __half* oh = g_wth + (size_t)mat * ISZ * ISZ;

    int nt = blockIdx.x * 32, kt = blockIdx.y * 32;
    int tx = threadIdx.x & 31, ty = threadIdx.x >> 5;   // 32 x 8

#pragma unroll
    for (int i = 0; i < 4; i++)
        tile[ty + i * 8][tx] = W[(size_t)(kt + ty + i * 8) * ISZ + nt + tx];
    __syncthreads();
#pragma unroll
    for (int i = 0; i < 4; i++) {
        int n = nt + ty + i * 8;
        oh[(size_t)n * ISZ + kt + tx] = __float2half_rn(tile[tx][ty + i * 8]);
    }
}

// ---------------------------------------------------------------------------
// Tensor-core GEMM via mma.sync, fp16 2-term split:
// C = (Ahi+Alo)[M,K] @ B[N,K]^T + bias, * mask   (B single fp16)
// 3 smem pieces (Ahi, Alo, B) -> stage 55296B, double buffer 110592B.
// 2 MMAs per (mt,nt,k16) instead of 3.
// ---------------------------------------------------------------------------
#define GM 4096
#define GN 1024
#define GK 1024
#define KST 64
#define NST (GK / KST)          // 16 stages
#define SK  72                  // smem stride in halves
#define PBY (128 * SK * 2)      // bytes per piece: 18432
#define STB (3 * PBY)           // per stage: 55296
#define GSMEM (2 * STB)         // 110592

__global__ __launch_bounds__(256, 1) void gemm_mma(
    const __half* __restrict__ Ahi, const __half* __restrict__ Alo,
    const __half* __restrict__ B,
    const float* __restrict__ bias, const float* __restrict__ mask,
    float* __restrict__ C)
{
    extern __shared__ __align__(128) char smc[];
    uint32_t sb = smem_u32(smc);

    int tid = threadIdx.x;
    int wid = tid >> 5, lane = tid & 31;
    int bn = blockIdx.x * 128, bm = blockIdx.y * 128;
    int warp_m = (wid >> 2) * 64;
    int warp_n = (wid & 3) * 32;

    const __half* srcs[3] = {
        Ahi + (size_t)bm * GK, Alo + (size_t)bm * GK,
        B + (size_t)bn * GK };

    auto load_stage = [&](int t, int s) {
        int k0 = t * KST;
        uint32_t dbase = sb + s * STB;
#pragma unroll
        for (int buf = 0; buf < 3; buf++) {
#pragma unroll
            for (int i = 0; i < 4; i++) {
                int chunk = tid + i * 256;          // 0..1023
                int r = chunk >> 3, c = chunk & 7;  // row, 16B chunk
                const void* src = srcs[buf] + (size_t)r * GK + k0 + c * 8;
                uint32_t dst = dbase + buf * PBY + r * (SK * 2) + c * 16;
                cp_async16(dst, src);
            }
        }
    };

    float acc[4][4][4];
#pragma unroll
    for (int i = 0; i < 4; i++)
#pragma unroll
        for (int j = 0; j < 4; j++)
#pragma unroll
            for (int r = 0; r < 4; r++) acc[i][j][r] = 0.f;

    int a_row = lane & 15;
    int a_kh  = (lane >> 4) * 16;
    int b_row = lane & 7;
    int b_kh  = ((lane >> 3) & 1) * 16;

    load_stage(0, 0);
    cp_commit();

    for (int t = 0; t < NST; t++) {
        int s = t & 1;
        if (t + 1 < NST) { load_stage(t + 1, s ^ 1); cp_commit(); cp_wait1(); }
        else             { cp_wait0(); }
        __syncthreads();

        uint32_t st = sb + s * STB;
#pragma unroll
        for (int k16 = 0; k16 < 4; k16++) {
            uint32_t kb = k16 * 32;
            uint32_t ah[4][4], al[4][4], bf[4][2];
#pragma unroll
            for (int mt = 0; mt < 4; mt++) {
                uint32_t ra = (warp_m + mt * 16 + a_row) * (SK * 2) + kb + a_kh;
                ldsm_x4(ah[mt][0], ah[mt][1], ah[mt][2], ah[mt][3], st + ra);
                ldsm_x4(al[mt][0], al[mt][1], al[mt][2], al[mt][3], st + PBY + ra);
            }
#pragma unroll
            for (int nt = 0; nt < 4; nt++) {
                uint32_t rb = (warp_n + nt * 8 + b_row) * (SK * 2) + kb + b_kh;
                ldsm_x2(bf[nt][0], bf[nt][1], st + 2 * PBY + rb);
            }
#pragma unroll
            for (int mt = 0; mt < 4; mt++)
#pragma unroll
                for (int nt = 0; nt < 4; nt++) {
                    mma_f16(acc[mt][nt], ah[mt], bf[nt]);
                    mma_f16(acc[mt][nt], al[mt], bf[nt]);
                }
        }
        __syncthreads();
    }

#pragma unroll
    for (int mt = 0; mt < 4; mt++) {
        int r0 = bm + warp_m + mt * 16 + (lane >> 2);
        int r1 = r0 + 8;
        float mk0 = mask[r0], mk1 = mask[r1];
        float* c0 = C + (size_t)r0 * GN;
        float* c1 = C + (size_t)r1 * GN;
#pragma unroll
        for (int nt = 0; nt < 4; nt++) {
            int col = bn + warp_n + nt * 8 + (lane & 3) * 2;
            float2 o0, o1;
            o0.x = (acc[mt][nt][0] + bias[col + 0]) * mk0;
            o0.y = (acc[mt][nt][1] + bias[col + 1]) * mk0;
            o1.x = (acc[mt][nt][2] + bias[col + 0]) * mk1;
            o1.y = (acc[mt][nt][3] + bias[col + 1]) * mk1;
            *(float2*)(c0 + col) = o0;
            *(float2*)(c1 + col) = o1;
        }
    }
}

// ---------------------------------------------------------------------------
// Flash attention on tensor cores (fp16 mma.sync), 2 CTAs/SM (proven R11).
// Q hi/lo persistent in smem; K,V single fp16.
// ---------------------------------------------------------------------------
#define AST 72   // smem row stride in halves (144 B)
#define ATTN_SMEM ((2 * 128 * AST + 2 * 64 * AST) * 2)   // 55296 bytes

__global__ __launch_bounds__(256, 2) void attn_mma(
    const float* __restrict__ Qw, const float* __restrict__ Kw,
    const float* __restrict__ Vw)
{
    extern __shared__ __align__(16) __half ash[];
    __half* Qh = ash;                         // [128][AST] persistent
    __half* Ql = ash + 128 * AST;             // [128][AST] persistent
    __half* Ks = ash + 2 * 128 * AST;         // [64][AST]
    __half* Vs = ash + 2 * 128 * AST + 64 * AST;

    int tid = threadIdx.x;
    int wid = tid >> 5, lane = tid & 31;
    int qb = (int)(gridDim.x - 1 - blockIdx.x);   // heavy blocks first
    int bh = blockIdx.y;
    int b = bh >> 4, h = bh & 15;

    size_t tokQ = (size_t)b * SEQ + qb * 128;
    int colBase = h * HDIM;

    // ---- stage Q (scaled by 0.125, split fp16 hi/lo) ----
#pragma unroll
    for (int i = 0; i < 8; i++) {
        int p = tid + i * 256;           // 0..2047 = 128 rows x 16 float4
        int r = p >> 4, c4 = p & 15;
        float4 qv = *(const float4*)(Qw + (tokQ + r) * ISZ + colBase + c4 * 4);
        float y[4] = { qv.x * 0.125f, qv.y * 0.125f, qv.z * 0.125f, qv.w * 0.125f };
#pragma unroll
        for (int e = 0; e < 4; e++) {
            __half hi = __float2half_rn(y[e]);
            Qh[r * AST + c4 * 4 + e] = hi;
            Ql[r * AST + c4 * 4 + e] = __float2half_rn(y[e] - __half2float(hi));
        }
    }
    __syncthreads();

    float O[8][4];
#pragma unroll
    for (int nt = 0; nt < 8; nt++)
#pragma unroll
        for (int e = 0; e < 4; e++) O[nt][e] = 0.f;
    float mrow[2] = { -3e38f, -3e38f };
    float lrow[2] = { 0.f, 0.f };

    uint32_t qb0 = smem_u32(Qh);
    uint32_t qb1 = smem_u32(Ql);
    uint32_t ksb = smem_u32(Ks);
    uint32_t vsb = smem_u32(Vs);
    int a_row = lane & 15;
    int a_kh  = (lane >> 4) * 16;
    int b_row = lane & 7;
    int b_kh  = ((lane >> 3) & 1) * 16;

    int nkt = 2 * qb + 2;
    for (int kt = 0; kt < nkt; kt++) {
        if (kt > 0) __syncthreads();    // prior tile fully consumed
        size_t tokK = (size_t)b * SEQ + kt * 64;
#pragma unroll
        for (int i = 0; i < 4; i++) {
            int p = tid + i * 256;       // 0..1023
            int r = p >> 4, c4 = p & 15;
            float4 kv = *(const float4*)(Kw + (tokK + r) * ISZ + colBase + c4 * 4);
            *(uint32_t*)(Ks + r * AST + c4 * 4)     = h2pack(kv.x, kv.y);
            *(uint32_t*)(Ks + r * AST + c4 * 4 + 2) = h2pack(kv.z, kv.w);
            float4 vv = *(const float4*)(Vw + (tokK + r) * ISZ + colBase + c4 * 4);
            *(uint32_t*)(Vs + r * AST + c4 * 4)     = h2pack(vv.x, vv.y);
            *(uint32_t*)(Vs + r * AST + c4 * 4 + 2) = h2pack(vv.z, vv.w);
        }
        __syncthreads();

        // ---- S = (Qhi+Qlo) @ K^T ----
        float S[8][4];
#pragma unroll
        for (int nt = 0; nt < 8; nt++)
#pragma unroll
            for (int e = 0; e < 4; e++) S[nt][e] = 0.f;

#pragma unroll
        for (int j = 0; j < 4; j++) {
            uint32_t qoff = (wid * 16 + a_row) * (AST * 2) + j * 32 + a_kh;
            uint32_t qfh[4], qfl[4];
            ldsm_x4(qfh[0], qfh[1], qfh[2], qfh[3], qb0 + qoff);
            ldsm_x4(qfl[0], qfl[1], qfl[2], qfl[3], qb1 + qoff);
#pragma unroll
            for (int nt = 0; nt < 8; nt++) {
                uint32_t kf[2];
                ldsm_x2(kf[0], kf[1], ksb + (nt * 8 + b_row) * (AST * 2) + j * 32 + b_kh);
                mma_f16(S[nt], qfh, kf);
                mma_f16(S[nt], qfl, kf);
            }
        }

        // ---- causal mask (diagonal tiles only) ----
        if (kt >= 2 * qb) {
            int Rb = qb * 128 + wid * 16 + (lane >> 2);
#pragma unroll
            for (int nt = 0; nt < 8; nt++)
#pragma unroll
                for (int e = 0; e < 4; e++) {
                    int R = Rb + (e >> 1) * 8;
                    int C = kt * 64 + nt * 8 + 2 * (lane & 3) + (e & 1);
                    if (C > R) S[nt][e] = -3e38f;
                }
        }

        // ---- online softmax ----
#pragma unroll
        for (int hh = 0; hh < 2; hh++) {
            float mx = -3e38f;
#pragma unroll
            for (int nt = 0; nt < 8; nt++) {
                mx = fmaxf(mx, S[nt][2 * hh]);
                mx = fmaxf(mx, S[nt][2 * hh + 1]);
            }
            mx = fmaxf(mx, __shfl_xor_sync(0xffffffffu, mx, 1));
            mx = fmaxf(mx, __shfl_xor_sync(0xffffffffu, mx, 2));

            float mnew = fmaxf(mrow[hh], mx);
            float corr = __expf(mrow[hh] - mnew);
            float ts = 0.f;
#pragma unroll
            for (int nt = 0; nt < 8; nt++) {
                float p0 = __expf(S[nt][2 * hh]     - mnew);
                float p1 = __expf(S[nt][2 * hh + 1] - mnew);
                S[nt][2 * hh]     = p0;
                S[nt][2 * hh + 1] = p1;
                ts += p0 + p1;
            }
            ts += __shfl_xor_sync(0xffffffffu, ts, 1);
            ts += __shfl_xor_sync(0xffffffffu, ts, 2);

            lrow[hh] = lrow[hh] * corr + ts;
            mrow[hh] = mnew;
#pragma unroll
            for (int nt = 0; nt < 8; nt++) {
                O[nt][2 * hh]     *= corr;
                O[nt][2 * hh + 1] *= corr;
            }
        }

        // ---- O += (Phi+Plo) @ V ----
#pragma unroll
        for (int j = 0; j < 4; j++) {
            uint32_t ph[4], pl[4];
#pragma unroll
            for (int r = 0; r < 4; r++) {
                int nt = 2 * j + (r >> 1);
                int e0 = (r & 1) * 2;
                float p0 = S[nt][e0], p1 = S[nt][e0 + 1];
                __half h0 = __float2half_rn(p0), h1 = __float2half_rn(p1);
                __half2 hp = __halves2half2(h0, h1);
                ph[r] = *(uint32_t*)&hp;
                pl[r] = h2pack(p0 - __half2float(h0), p1 - __half2float(h1));
            }
#pragma unroll
            for (int nt = 0; nt < 8; nt++) {
                uint32_t vf[2];
                ldsm_x2t(vf[0], vf[1], vsb + (j * 16 + (lane & 15)) * (AST * 2) + nt * 16);
                mma_f16(O[nt], ph, vf);
                mma_f16(O[nt], pl, vf);
            }
        }
    }

    // ---- epilogue: normalize, split fp16 hi/lo for the Wo GEMM ----
#pragma unroll
    for (int hh = 0; hh < 2; hh++) {
        float inv = 1.f / lrow[hh];
        size_t tok = tokQ + wid * 16 + (lane >> 2) + 8 * hh;
#pragma unroll
        for (int nt = 0; nt < 8; nt++) {
            int col = colBase + nt * 8 + 2 * (lane & 3);
            float y0 = O[nt][2 * hh] * inv;
            float y1 = O[nt][2 * hh + 1] * inv;
            __half h0 = __float2half_rn(y0);
            __half h1 = __float2half_rn(y1);
            __half2 hv = __halves2half2(h0, h1);
            __half2 lv = __halves2half2(__float2half_rn(y0 - __half2float(h0)),
                                        __float2half_rn(y1 - __half2float(h1)));
            *(__half2*)(g_aoh + tok * ISZ + col) = hv;
            *(__half2*)(g_aol + tok * ISZ + col) = lv;
        }
    }
}

// ---------------------------------------------------------------------------
// Launch
// ---------------------------------------------------------------------------
template <typename T> static T* symaddr(const void* sym) {
    void* p; cudaGetSymbolAddress(&p, sym); return (T*)p;
}

extern "C" void kernel_launch(void* const* d_in, const int* in_sizes, int n_in,
                              void* d_out, int out_size)
{
    const float* q       = (const float*)d_in[0];
    const float* k       = (const float*)d_in[1];
    const float* v       = (const float*)d_in[2];
    const float* q_mask  = (const float*)d_in[3];
    const float* kv_mask = (const float*)d_in[4];
    const float* ln_g    = (const float*)d_in[6];
    const float* ln_b    = (const float*)d_in[7];
    const float* Wq      = (const float*)d_in[8];
    const float* bq      = (const float*)d_in[9];
    const float* Wk      = (const float*)d_in[10];
    const float* bk      = (const float*)d_in[11];
    const float* Wv      = (const float*)d_in[12];
    const float* bv      = (const float*)d_in[13];
    const float* Wo      = (const float*)d_in[14];
    const float* bo      = (const float*)d_in[15];
    float* out = (float*)d_out;

    __half* xhi = symaddr<__half>(g_xhi);
    __half* xlo = symaddr<__half>(g_xlo);
    __half* wth = symaddr<__half>(g_wth);
    float*  qw  = symaddr<float>(g_qw);
    float*  kw  = symaddr<float>(g_kw);
    float*  vw  = symaddr<float>(g_vw);
    __half* aoh = symaddr<__half>(g_aoh);
    __half* aol = symaddr<__half>(g_aol);

    const size_t T = (size_t)ROWS * ISZ;
    const size_t WSZ = (size_t)ISZ * ISZ;

    // 1) LayerNorm -> split fp16
    ln3_kernel<<<3 * ROWS, 256>>>(q, k, v, ln_g, ln_b);

    // 2) Weight transpose -> fp16
    wconv_kernel<<<dim3(32, 32, 4), 256>>>(Wq, Wk, Wv, Wo);

    // 3) QKV projections (mma.sync, fp16 2-term)
    cudaFuncSetAttribute(gemm_mma,
                         cudaFuncAttributeMaxDynamicSharedMemorySize, GSMEM);
    dim3 ggrid(GN / 128, GM / 128);
    gemm_mma<<<ggrid, 256, GSMEM>>>(xhi,         xlo,         wth,           bq, q_mask,  qw);
    gemm_mma<<<ggrid, 256, GSMEM>>>(xhi + T,     xlo + T,     wth + WSZ,     bk, kv_mask, kw);
    gemm_mma<<<ggrid, 256, GSMEM>>>(xhi + 2 * T, xlo + 2 * T, wth + 2 * WSZ, bv, kv_mask, vw);

    // 4) Flash attention on tensor cores -> split fp16 (2 CTAs/SM)
    cudaFuncSetAttribute(attn_mma,
                         cudaFuncAttributeMaxDynamicSharedMemorySize, ATTN_SMEM);
    dim3 agrid(SEQ / 128, BATCH * NHEAD);
    attn_mma<<<agrid, 256, ATTN_SMEM>>>(qw, kw, vw);

    // 5) Output projection straight into d_out
    gemm_mma<<<ggrid, 256, GSMEM>>>(aoh, aol, wth + 3 * WSZ, bo, kv_mask, out);
}

// round 15
// speedup vs baseline: 1.3309x; 1.0218x over previous
#include <cuda_runtime.h>
#include <cuda_bf16.h>
#include <cuda_fp16.h>
#include <math.h>
#include <stdint.h>

// Problem constants
#define BATCH 2
#define SEQ   2048
#define ISZ   1024
#define NHEAD 16
#define HDIM  64
#define ROWS  (BATCH*SEQ)      // 4096

// ---------------------------------------------------------------------------
// Scratch (device globals: allocation-free per harness rules)
// ---------------------------------------------------------------------------
__device__ __half g_xhi[(size_t)3*ROWS*ISZ];   // LN outputs hi (q,k,v)
__device__ __half g_xlo[(size_t)3*ROWS*ISZ];   // LN outputs lo
__device__ __half g_wth[(size_t)4*ISZ*ISZ];    // W^T fp16 (Wq,Wk,Wv,Wo)
__device__ float  g_qw[(size_t)ROWS*ISZ];
__device__ float  g_kw[(size_t)ROWS*ISZ];
__device__ float  g_vw[(size_t)ROWS*ISZ];
__device__ __half g_aoh[(size_t)ROWS*ISZ];     // attention out hi
__device__ __half g_aol[(size_t)ROWS*ISZ];     // attention out lo

// ---------------------------------------------------------------------------
// PTX helpers (Ampere-compatible: cp.async, ldmatrix, mma.sync)
// ---------------------------------------------------------------------------
__device__ __forceinline__ uint32_t smem_u32(const void* p) {
    return (uint32_t)__cvta_generic_to_shared(p);
}
__device__ __forceinline__ void cp_async16(uint32_t dst, const void* src) {
    asm volatile("cp.async.cg.shared.global [%0], [%1], 16;\n" :: "r"(dst), "l"(src));
}
__device__ __forceinline__ void cp_commit() {
    asm volatile("cp.async.commit_group;\n");
}
__device__ __forceinline__ void cp_wait1() {
    asm volatile("cp.async.wait_group 1;\n");
}
__device__ __forceinline__ void cp_wait0() {
    asm volatile("cp.async.wait_group 0;\n");
}
__device__ __forceinline__ void ldsm_x4(uint32_t& r0, uint32_t& r1,
                                        uint32_t& r2, uint32_t& r3, uint32_t a) {
    asm volatile("ldmatrix.sync.aligned.m8n8.x4.shared.b16 {%0,%1,%2,%3}, [%4];"
                 : "=r"(r0), "=r"(r1), "=r"(r2), "=r"(r3) : "r"(a));
}
__device__ __forceinline__ void ldsm_x2(uint32_t& r0, uint32_t& r1, uint32_t a) {
    asm volatile("ldmatrix.sync.aligned.m8n8.x2.shared.b16 {%0,%1}, [%2];"
                 : "=r"(r0), "=r"(r1) : "r"(a));
}
__device__ __forceinline__ void ldsm_x2t(uint32_t& r0, uint32_t& r1, uint32_t a) {
    asm volatile("ldmatrix.sync.aligned.m8n8.x2.trans.shared.b16 {%0,%1}, [%2];"
                 : "=r"(r0), "=r"(r1) : "r"(a));
}
__device__ __forceinline__ void mma_f16(float* d, const uint32_t* a, const uint32_t* b) {
    asm volatile("mma.sync.aligned.m16n8k16.row.col.f32.f16.f16.f32 "
                 "{%0,%1,%2,%3}, {%4,%5,%6,%7}, {%8,%9}, {%0,%1,%2,%3};"
                 : "+f"(d[0]), "+f"(d[1]), "+f"(d[2]), "+f"(d[3])
                 : "r"(a[0]), "r"(a[1]), "r"(a[2]), "r"(a[3]), "r"(b[0]), "r"(b[1]));
}
__device__ __forceinline__ uint32_t h2pack(float a, float b) {
    __half2 h = __floats2half2_rn(a, b);
    return *(uint32_t*)&h;
}

// ---------------------------------------------------------------------------
// LayerNorm: one block per row; writes split-fp16 (hi, lo)
// ---------------------------------------------------------------------------
__global__ __launch_bounds__(256) void ln3_kernel(
    const float* __restrict__ q, const float* __restrict__ k,
    const float* __restrict__ v, const float* __restrict__ g,
    const float* __restrict__ beta)
{
    __shared__ float sbuf[8];
    int which = blockIdx.x >> 12;
    int row   = blockIdx.x & 4095;
    const float* x =
        (which == 0 ? q : which == 1 ? k : v) + (size_t)row * ISZ;
    __half* ohi = g_xhi + (size_t)which * ROWS * ISZ + (size_t)row * ISZ;
    __half* olo = g_xlo + (size_t)which * ROWS * ISZ + (size_t)row * ISZ;

    int tid  = threadIdx.x;
    int lane = tid & 31, wid = tid >> 5;

    float vals[4];
    float s = 0.f;
#pragma unroll
    for (int i = 0; i < 4; i++) { vals[i] = x[tid + i * 256]; s += vals[i]; }
#pragma unroll
    for (int o = 16; o > 0; o >>= 1) s += __shfl_xor_sync(0xffffffffu, s, o);
    if (lane == 0) sbuf[wid] = s;
    __syncthreads();
    if (tid < 32) {
        float t = (tid < 8) ? sbuf[tid] : 0.f;
#pragma unroll
        for (int o = 4; o > 0; o >>= 1) t += __shfl_xor_sync(0xffffffffu, t, o);
        if (tid == 0) sbuf[0] = t;
    }
    __syncthreads();
    float mu = sbuf[0] * (1.f / ISZ);
    __syncthreads();

    float sq = 0.f;
#pragma unroll
    for (int i = 0; i < 4; i++) { float d = vals[i] - mu; sq += d * d; }
#pragma unroll
    for (int o = 16; o > 0; o >>= 1) sq += __shfl_xor_sync(0xffffffffu, sq, o);
    if (lane == 0) sbuf[wid] = sq;
    __syncthreads();
    if (tid < 32) {
        float t = (tid < 8) ? sbuf[tid] : 0.f;
#pragma unroll
        for (int o = 4; o > 0; o >>= 1) t += __shfl_xor_sync(0xffffffffu, t, o);
        if (tid == 0) sbuf[0] = t;
    }
    __syncthreads();
    float rstd = rsqrtf(sbuf[0] * (1.f / ISZ) + 1e-5f);

#pragma unroll
    for (int i = 0; i < 4; i++) {
        int idx = tid + i * 256;
        float y = (vals[i] - mu) * rstd * g[idx] + beta[idx];
        __half hi = __float2half_rn(y);
        ohi[idx] = hi;
        olo[idx] = __float2half_rn(y - __half2float(hi));
    }
}

// ---------------------------------------------------------------------------
// Weight transpose: W[K][N] fp32 -> Wt[N][K] fp16
// ---------------------------------------------------------------------------
__global__ __launch_bounds__(256) void wconv_kernel(
    const float* __restrict__ W0, const float* __restrict__ W1,
    const float* __restrict__ W2, const float* __restrict__ W3)
{
    __shared__ float tile[32][33];
    int mat = blockIdx.z;
    const float* W = (mat == 0 ? W0 : mat == 1 ? W1 : mat == 2 ? W2 : W3);
    __half* oh = g_wth + (size_t)mat * ISZ * ISZ;

    int nt = blockIdx.x * 32, kt = blockIdx.y * 32;
    int tx = threadIdx.x & 31, ty = threadIdx.x >> 5;   // 32 x 8

#pragma unroll
    for (int i = 0; i < 4; i++)
        tile[ty + i * 8][tx] = W[(size_t)(kt + ty + i * 8) * ISZ + nt + tx];
    __syncthreads();
#pragma unroll
    for (int i = 0; i < 4; i++) {
        int n = nt + ty + i * 8;
        oh[(size_t)n * ISZ + kt + tx] = __float2half_rn(tile[tx][ty + i * 8]);
    }
}

// ---------------------------------------------------------------------------
// Tensor-core GEMM via mma.sync, fp16 2-term split, 3-STAGE cp.async pipeline.
// blockIdx.z selects operand set (fused QKV launch); strides offset A and B.
// One __syncthreads per stage (vs 2 in the 2-stage version).
// ---------------------------------------------------------------------------
#define GM 4096
#define GN 1024
#define GK 1024
#define KST 64
#define NST (GK / KST)          // 16 stages
#define SK  72                  // smem stride in halves
#define PBY (128 * SK * 2)      // bytes per piece: 18432
#define STB (3 * PBY)           // per stage: 55296
#define GSMEM (3 * STB)         // 165888 (3-stage)

__global__ __launch_bounds__(256, 1) void gemm_mma(
    const __half* __restrict__ Abase_hi, const __half* __restrict__ Abase_lo,
    const __half* __restrict__ Bbase,
    const float* __restrict__ bias0, const float* __restrict__ mask0, float* __restrict__ C0,
    const float* __restrict__ bias1, const float* __restrict__ mask1, float* __restrict__ C1,
    const float* __restrict__ bias2, const float* __restrict__ mask2, float* __restrict__ C2)
{
    extern __shared__ __align__(128) char smc[];
    uint32_t sb = smem_u32(smc);

    int tid = threadIdx.x;
    int wid = tid >> 5, lane = tid & 31;
    int bn = blockIdx.x * 128, bm = blockIdx.y * 128;
    int z = blockIdx.z;
    int warp_m = (wid >> 2) * 64;
    int warp_n = (wid & 3) * 32;

    const float* bias = (z == 0) ? bias0 : (z == 1) ? bias1 : bias2;
    const float* mask = (z == 0) ? mask0 : (z == 1) ? mask1 : mask2;
    float* C = (z == 0) ? C0 : (z == 1) ? C1 : C2;

    const size_t TA = (size_t)ROWS * ISZ;   // A z-stride
    const size_t TB = (size_t)ISZ * ISZ;    // B z-stride
    const __half* srcs[3] = {
        Abase_hi + (size_t)z * TA + (size_t)bm * GK,
        Abase_lo + (size_t)z * TA + (size_t)bm * GK,
        Bbase    + (size_t)z * TB + (size_t)bn * GK };

    auto load_stage = [&](int t, int s) {
        int k0 = t * KST;
        uint32_t dbase = sb + s * STB;
#pragma unroll
        for (int buf = 0; buf < 3; buf++) {
#pragma unroll
            for (int i = 0; i < 4; i++) {
                int chunk = tid + i * 256;          // 0..1023
                int r = chunk >> 3, c = chunk & 7;  // row, 16B chunk
                const void* src = srcs[buf] + (size_t)r * GK + k0 + c * 8;
                uint32_t dst = dbase + buf * PBY + r * (SK * 2) + c * 16;
                cp_async16(dst, src);
            }
        }
    };

    float acc[4][4][4];
#pragma unroll
    for (int i = 0; i < 4; i++)
#pragma unroll
        for (int j = 0; j < 4; j++)
#pragma unroll
            for (int r = 0; r < 4; r++) acc[i][j][r] = 0.f;

    int a_row = lane & 15;
    int a_kh  = (lane >> 4) * 16;
    int b_row = lane & 7;
    int b_kh  = ((lane >> 3) & 1) * 16;

    load_stage(0, 0); cp_commit();
    load_stage(1, 1); cp_commit();

    int sbuf_idx = 0;
    for (int t = 0; t < NST; t++) {
        if (t < NST - 1) cp_wait1();    // stage t complete (t+1 may be in flight)
        else             cp_wait0();
        __syncthreads();                 // data visible; all warps done with t-1
        if (t + 2 < NST) {
            int s2 = (sbuf_idx + 2 >= 3) ? sbuf_idx + 2 - 3 : sbuf_idx + 2;
            load_stage(t + 2, s2);       // overwrites buffer of stage t-1 (safe)
            cp_commit();
        }

        uint32_t st = sb + sbuf_idx * STB;
#pragma unroll
        for (int k16 = 0; k16 < 4; k16++) {
            uint32_t kb = k16 * 32;
            uint32_t ah[4][4], al[4][4], bf[4][2];
#pragma unroll
            for (int mt = 0; mt < 4; mt++) {
                uint32_t ra = (warp_m + mt * 16 + a_row) * (SK * 2) + kb + a_kh;
                ldsm_x4(ah[mt][0], ah[mt][1], ah[mt][2], ah[mt][3], st + ra);
                ldsm_x4(al[mt][0], al[mt][1], al[mt][2], al[mt][3], st + PBY + ra);
            }
#pragma unroll
            for (int nt = 0; nt < 4; nt++) {
                uint32_t rb = (warp_n + nt * 8 + b_row) * (SK * 2) + kb + b_kh;
                ldsm_x2(bf[nt][0], bf[nt][1], st + 2 * PBY + rb);
            }
#pragma unroll
            for (int mt = 0; mt < 4; mt++)
#pragma unroll
                for (int nt = 0; nt < 4; nt++) {
                    mma_f16(acc[mt][nt], ah[mt], bf[nt]);
                    mma_f16(acc[mt][nt], al[mt], bf[nt]);
                }
        }
        sbuf_idx = (sbuf_idx + 1 >= 3) ? 0 : sbuf_idx + 1;
    }

#pragma unroll
    for (int mt = 0; mt < 4; mt++) {
        int r0 = bm + warp_m + mt * 16 + (lane >> 2);
        int r1 = r0 + 8;
        float mk0 = mask[r0], mk1 = mask[r1];
        float* c0 = C + (size_t)r0 * GN;
        float* c1 = C + (size_t)r1 * GN;
#pragma unroll
        for (int nt = 0; nt < 4; nt++) {
            int col = bn + warp_n + nt * 8 + (lane & 3) * 2;
            float2 o0, o1;
            o0.x = (acc[mt][nt][0] + bias[col + 0]) * mk0;
            o0.y = (acc[mt][nt][1] + bias[col + 1]) * mk0;
            o1.x = (acc[mt][nt][2] + bias[col + 0]) * mk1;
            o1.y = (acc[mt][nt][3] + bias[col + 1]) * mk1;
            *(float2*)(c0 + col) = o0;
            *(float2*)(c1 + col) = o1;
        }
    }
}

// ---------------------------------------------------------------------------
// Flash attention on tensor cores (fp16 mma.sync), 2 CTAs/SM — unchanged R12.
// ---------------------------------------------------------------------------
#define AST 72   // smem row stride in halves (144 B)
#define ATTN_SMEM ((2 * 128 * AST + 2 * 64 * AST) * 2)   // 55296 bytes

__global__ __launch_bounds__(256, 2) void attn_mma(
    const float* __restrict__ Qw, const float* __restrict__ Kw,
    const float* __restrict__ Vw)
{
    extern __shared__ __align__(16) __half ash[];
    __half* Qh = ash;                         // [128][AST] persistent
    __half* Ql = ash + 128 * AST;             // [128][AST] persistent
    __half* Ks = ash + 2 * 128 * AST;         // [64][AST]
    __half* Vs = ash + 2 * 128 * AST + 64 * AST;

    int tid = threadIdx.x;
    int wid = tid >> 5, lane = tid & 31;
    int qb = (int)(gridDim.x - 1 - blockIdx.x);   // heavy blocks first
    int bh = blockIdx.y;
    int b = bh >> 4, h = bh & 15;

    size_t tokQ = (size_t)b * SEQ + qb * 128;
    int colBase = h * HDIM;

#pragma unroll
    for (int i = 0; i < 8; i++) {
        int p = tid + i * 256;
        int r = p >> 4, c4 = p & 15;
        float4 qv = *(const float4*)(Qw + (tokQ + r) * ISZ + colBase + c4 * 4);
        float y[4] = { qv.x * 0.125f, qv.y * 0.125f, qv.z * 0.125f, qv.w * 0.125f };
#pragma unroll
        for (int e = 0; e < 4; e++) {
            __half hi = __float2half_rn(y[e]);
            Qh[r * AST + c4 * 4 + e] = hi;
            Ql[r * AST + c4 * 4 + e] = __float2half_rn(y[e] - __half2float(hi));
        }
    }
    __syncthreads();

    float O[8][4];
#pragma unroll
    for (int nt = 0; nt < 8; nt++)
#pragma unroll
        for (int e = 0; e < 4; e++) O[nt][e] = 0.f;
    float mrow[2] = { -3e38f, -3e38f };
    float lrow[2] = { 0.f, 0.f };

    uint32_t qb0 = smem_u32(Qh);
    uint32_t qb1 = smem_u32(Ql);
    uint32_t ksb = smem_u32(Ks);
    uint32_t vsb = smem_u32(Vs);
    int a_row = lane & 15;
    int a_kh  = (lane >> 4) * 16;
    int b_row = lane & 7;
    int b_kh  = ((lane >> 3) & 1) * 16;

    int nkt = 2 * qb + 2;
    for (int kt = 0; kt < nkt; kt++) {
        if (kt > 0) __syncthreads();
        size_t tokK = (size_t)b * SEQ + kt * 64;
#pragma unroll
        for (int i = 0; i < 4; i++) {
            int p = tid + i * 256;
            int r = p >> 4, c4 = p & 15;
            float4 kv = *(const float4*)(Kw + (tokK + r) * ISZ + colBase + c4 * 4);
            *(uint32_t*)(Ks + r * AST + c4 * 4)     = h2pack(kv.x, kv.y);
            *(uint32_t*)(Ks + r * AST + c4 * 4 + 2) = h2pack(kv.z, kv.w);
            float4 vv = *(const float4*)(Vw + (tokK + r) * ISZ + colBase + c4 * 4);
            *(uint32_t*)(Vs + r * AST + c4 * 4)     = h2pack(vv.x, vv.y);
            *(uint32_t*)(Vs + r * AST + c4 * 4 + 2) = h2pack(vv.z, vv.w);
        }
        __syncthreads();

        float S[8][4];
#pragma unroll
        for (int nt = 0; nt < 8; nt++)
#pragma unroll
            for (int e = 0; e < 4; e++) S[nt][e] = 0.f;

#pragma unroll
        for (int j = 0; j < 4; j++) {
            uint32_t qoff = (wid * 16 + a_row) * (AST * 2) + j * 32 + a_kh;
            uint32_t qfh[4], qfl[4];
            ldsm_x4(qfh[0], qfh[1], qfh[2], qfh[3], qb0 + qoff);
            ldsm_x4(qfl[0], qfl[1], qfl[2], qfl[3], qb1 + qoff);
#pragma unroll
            for (int nt = 0; nt < 8; nt++) {
                uint32_t kf[2];
                ldsm_x2(kf[0], kf[1], ksb + (nt * 8 + b_row) * (AST * 2) + j * 32 + b_kh);
                mma_f16(S[nt], qfh, kf);
                mma_f16(S[nt], qfl, kf);
            }
        }

        if (kt >= 2 * qb) {
            int Rb = qb * 128 + wid * 16 + (lane >> 2);
#pragma unroll
            for (int nt = 0; nt < 8; nt++)
#pragma unroll
                for (int e = 0; e < 4; e++) {
                    int R = Rb + (e >> 1) * 8;
                    int C = kt * 64 + nt * 8 + 2 * (lane & 3) + (e & 1);
                    if (C > R) S[nt][e] = -3e38f;
                }
        }

#pragma unroll
        for (int hh = 0; hh < 2; hh++) {
            float mx = -3e38f;
#pragma unroll
            for (int nt = 0; nt < 8; nt++) {
                mx = fmaxf(mx, S[nt][2 * hh]);
                mx = fmaxf(mx, S[nt][2 * hh + 1]);
            }
            mx = fmaxf(mx, __shfl_xor_sync(0xffffffffu, mx, 1));
            mx = fmaxf(mx, __shfl_xor_sync(0xffffffffu, mx, 2));

            float mnew = fmaxf(mrow[hh], mx);
            float corr = __expf(mrow[hh] - mnew);
            float ts = 0.f;
#pragma unroll
            for (int nt = 0; nt < 8; nt++) {
                float p0 = __expf(S[nt][2 * hh]     - mnew);
                float p1 = __expf(S[nt][2 * hh + 1] - mnew);
                S[nt][2 * hh]     = p0;
                S[nt][2 * hh + 1] = p1;
                ts += p0 + p1;
            }
            ts += __shfl_xor_sync(0xffffffffu, ts, 1);
            ts += __shfl_xor_sync(0xffffffffu, ts, 2);

            lrow[hh] = lrow[hh] * corr + ts;
            mrow[hh] = mnew;
#pragma unroll
            for (int nt = 0; nt < 8; nt++) {
                O[nt][2 * hh]     *= corr;
                O[nt][2 * hh + 1] *= corr;
            }
        }

#pragma unroll
        for (int j = 0; j < 4; j++) {
            uint32_t ph[4], pl[4];
#pragma unroll
            for (int r = 0; r < 4; r++) {
                int nt = 2 * j + (r >> 1);
                int e0 = (r & 1) * 2;
                float p0 = S[nt][e0], p1 = S[nt][e0 + 1];
                __half h0 = __float2half_rn(p0), h1 = __float2half_rn(p1);
                __half2 hp = __halves2half2(h0, h1);
                ph[r] = *(uint32_t*)&hp;
                pl[r] = h2pack(p0 - __half2float(h0), p1 - __half2float(h1));
            }
#pragma unroll
            for (int nt = 0; nt < 8; nt++) {
                uint32_t vf[2];
                ldsm_x2t(vf[0], vf[1], vsb + (j * 16 + (lane & 15)) * (AST * 2) + nt * 16);
                mma_f16(O[nt], ph, vf);
                mma_f16(O[nt], pl, vf);
            }
        }
    }

#pragma unroll
    for (int hh = 0; hh < 2; hh++) {
        float inv = 1.f / lrow[hh];
        size_t tok = tokQ + wid * 16 + (lane >> 2) + 8 * hh;
#pragma unroll
        for (int nt = 0; nt < 8; nt++) {
            int col = colBase + nt * 8 + 2 * (lane & 3);
            float y0 = O[nt][2 * hh] * inv;
            float y1 = O[nt][2 * hh + 1] * inv;
            __half h0 = __float2half_rn(y0);
            __half h1 = __float2half_rn(y1);
            __half2 hv = __halves2half2(h0, h1);
            __half2 lv = __halves2half2(__float2half_rn(y0 - __half2float(h0)),
                                        __float2half_rn(y1 - __half2float(h1)));
            *(__half2*)(g_aoh + tok * ISZ + col) = hv;
            *(__half2*)(g_aol + tok * ISZ + col) = lv;
        }
    }
}

// ---------------------------------------------------------------------------
// Launch
// ---------------------------------------------------------------------------
template <typename T> static T* symaddr(const void* sym) {
    void* p; cudaGetSymbolAddress(&p, sym); return (T*)p;
}

extern "C" void kernel_launch(void* const* d_in, const int* in_sizes, int n_in,
                              void* d_out, int out_size)
{
    const float* q       = (const float*)d_in[0];
    const float* k       = (const float*)d_in[1];
    const float* v       = (const float*)d_in[2];
    const float* q_mask  = (const float*)d_in[3];
    const float* kv_mask = (const float*)d_in[4];
    const float* ln_g    = (const float*)d_in[6];
    const float* ln_b    = (const float*)d_in[7];
    const float* Wq      = (const float*)d_in[8];
    const float* bq      = (const float*)d_in[9];
    const float* Wk      = (const float*)d_in[10];
    const float* bk      = (const float*)d_in[11];
    const float* Wv      = (const float*)d_in[12];
    const float* bv      = (const float*)d_in[13];
    const float* Wo      = (const float*)d_in[14];
    const float* bo      = (const float*)d_in[15];
    float* out = (float*)d_out;

    __half* xhi = symaddr<__half>(g_xhi);
    __half* xlo = symaddr<__half>(g_xlo);
    __half* wth = symaddr<__half>(g_wth);
    float*  qw  = symaddr<float>(g_qw);
    float*  kw  = symaddr<float>(g_kw);
    float*  vw  = symaddr<float>(g_vw);
    __half* aoh = symaddr<__half>(g_aoh);
    __half* aol = symaddr<__half>(g_aol);

    const size_t WSZ = (size_t)ISZ * ISZ;

    // 1) LayerNorm -> split fp16
    ln3_kernel<<<3 * ROWS, 256>>>(q, k, v, ln_g, ln_b);

    // 2) Weight transpose -> fp16
    wconv_kernel<<<dim3(32, 32, 4), 256>>>(Wq, Wk, Wv, Wo);

    // 3) QKV projections: one fused launch (z = q,k,v), 3-stage pipeline
    cudaFuncSetAttribute(gemm_mma,
                         cudaFuncAttributeMaxDynamicSharedMemorySize, GSMEM);
    dim3 qkvgrid(GN / 128, GM / 128, 3);
    gemm_mma<<<qkvgrid, 256, GSMEM>>>(
        xhi, xlo, wth,
        bq, q_mask,  qw,
        bk, kv_mask, kw,
        bv, kv_mask, vw);

    // 4) Flash attention on tensor cores -> split fp16 (2 CTAs/SM)
    cudaFuncSetAttribute(attn_mma,
                         cudaFuncAttributeMaxDynamicSharedMemorySize, ATTN_SMEM);
    dim3 agrid(SEQ / 128, BATCH * NHEAD);
    attn_mma<<<agrid, 256, ATTN_SMEM>>>(qw, kw, vw);

    // 5) Output projection straight into d_out (z grid = 1)
    dim3 ogrid(GN / 128, GM / 128, 1);
    gemm_mma<<<ogrid, 256, GSMEM>>>(
        aoh, aol, wth + 3 * WSZ,
        bo, kv_mask, out,
        bo, kv_mask, out,
        bo, kv_mask, out);
}

// round 16
// speedup vs baseline: 1.8395x; 1.3821x over previous
#include <cuda_runtime.h>
#include <cuda_bf16.h>
#include <cuda_fp16.h>
#include <math.h>
#include <stdint.h>

// Problem constants
#define BATCH 2
#define SEQ   2048
#define ISZ   1024
#define NHEAD 16
#define HDIM  64
#define ROWS  (BATCH*SEQ)      // 4096

// ---------------------------------------------------------------------------
// Scratch (device globals: allocation-free per harness rules)
// ---------------------------------------------------------------------------
__device__ __half g_xh[(size_t)3*ROWS*ISZ];    // LN outputs fp16 (q,k,v)
__device__ __half g_wth[(size_t)4*ISZ*ISZ];    // W^T fp16 (Wq,Wk,Wv,Wo)
__device__ float  g_qw[(size_t)ROWS*ISZ];
__device__ float  g_kw[(size_t)ROWS*ISZ];
__device__ float  g_vw[(size_t)ROWS*ISZ];
__device__ __half g_ao[(size_t)ROWS*ISZ];      // attention out fp16

// ---------------------------------------------------------------------------
// PTX helpers (Ampere-compatible: cp.async, ldmatrix, mma.sync)
// ---------------------------------------------------------------------------
__device__ __forceinline__ uint32_t smem_u32(const void* p) {
    return (uint32_t)__cvta_generic_to_shared(p);
}
__device__ __forceinline__ void cp_async16(uint32_t dst, const void* src) {
    asm volatile("cp.async.cg.shared.global [%0], [%1], 16;\n" :: "r"(dst), "l"(src));
}
__device__ __forceinline__ void cp_commit() {
    asm volatile("cp.async.commit_group;\n");
}
__device__ __forceinline__ void cp_wait1() {
    asm volatile("cp.async.wait_group 1;\n");
}
__device__ __forceinline__ void cp_wait0() {
    asm volatile("cp.async.wait_group 0;\n");
}
__device__ __forceinline__ void ldsm_x4(uint32_t& r0, uint32_t& r1,
                                        uint32_t& r2, uint32_t& r3, uint32_t a) {
    asm volatile("ldmatrix.sync.aligned.m8n8.x4.shared.b16 {%0,%1,%2,%3}, [%4];"
                 : "=r"(r0), "=r"(r1), "=r"(r2), "=r"(r3) : "r"(a));
}
__device__ __forceinline__ void ldsm_x2(uint32_t& r0, uint32_t& r1, uint32_t a) {
    asm volatile("ldmatrix.sync.aligned.m8n8.x2.shared.b16 {%0,%1}, [%2];"
                 : "=r"(r0), "=r"(r1) : "r"(a));
}
__device__ __forceinline__ void ldsm_x2t(uint32_t& r0, uint32_t& r1, uint32_t a) {
    asm volatile("ldmatrix.sync.aligned.m8n8.x2.trans.shared.b16 {%0,%1}, [%2];"
                 : "=r"(r0), "=r"(r1) : "r"(a));
}
__device__ __forceinline__ void mma_f16(float* d, const uint32_t* a, const uint32_t* b) {
    asm volatile("mma.sync.aligned.m16n8k16.row.col.f32.f16.f16.f32 "
                 "{%0,%1,%2,%3}, {%4,%5,%6,%7}, {%8,%9}, {%0,%1,%2,%3};"
                 : "+f"(d[0]), "+f"(d[1]), "+f"(d[2]), "+f"(d[3])
                 : "r"(a[0]), "r"(a[1]), "r"(a[2]), "r"(a[3]), "r"(b[0]), "r"(b[1]));
}
__device__ __forceinline__ uint32_t h2pack(float a, float b) {
    __half2 h = __floats2half2_rn(a, b);
    return *(uint32_t*)&h;
}

// ---------------------------------------------------------------------------
// LayerNorm: one block per row; writes fp16
// ---------------------------------------------------------------------------
__global__ __launch_bounds__(256) void ln3_kernel(
    const float* __restrict__ q, const float* __restrict__ k,
    const float* __restrict__ v, const float* __restrict__ g,
    const float* __restrict__ beta)
{
    __shared__ float sbuf[8];
    int which = blockIdx.x >> 12;
    int row   = blockIdx.x & 4095;
    const float* x =
        (which == 0 ? q : which == 1 ? k : v) + (size_t)row * ISZ;
    __half* oh = g_xh + (size_t)which * ROWS * ISZ + (size_t)row * ISZ;

    int tid  = threadIdx.x;
    int lane = tid & 31, wid = tid >> 5;

    float vals[4];
    float s = 0.f;
#pragma unroll
    for (int i = 0; i < 4; i++) { vals[i] = x[tid + i * 256]; s += vals[i]; }
#pragma unroll
    for (int o = 16; o > 0; o >>= 1) s += __shfl_xor_sync(0xffffffffu, s, o);
    if (lane == 0) sbuf[wid] = s;
    __syncthreads();
    if (tid < 32) {
        float t = (tid < 8) ? sbuf[tid] : 0.f;
#pragma unroll
        for (int o = 4; o > 0; o >>= 1) t += __shfl_xor_sync(0xffffffffu, t, o);
        if (tid == 0) sbuf[0] = t;
    }
    __syncthreads();
    float mu = sbuf[0] * (1.f / ISZ);
    __syncthreads();

    float sq = 0.f;
#pragma unroll
    for (int i = 0; i < 4; i++) { float d = vals[i] - mu; sq += d * d; }
#pragma unroll
    for (int o = 16; o > 0; o >>= 1) sq += __shfl_xor_sync(0xffffffffu, sq, o);
    if (lane == 0) sbuf[wid] = sq;
    __syncthreads();
    if (tid < 32) {
        float t = (tid < 8) ? sbuf[tid] : 0.f;
#pragma unroll
        for (int o = 4; o > 0; o >>= 1) t += __shfl_xor_sync(0xffffffffu, t, o);
        if (tid == 0) sbuf[0] = t;
    }
    __syncthreads();
    float rstd = rsqrtf(sbuf[0] * (1.f / ISZ) + 1e-5f);

#pragma unroll
    for (int i = 0; i < 4; i++) {
        int idx = tid + i * 256;
        float y = (vals[i] - mu) * rstd * g[idx] + beta[idx];
        oh[idx] = __float2half_rn(y);
    }
}

// ---------------------------------------------------------------------------
// Weight transpose: W[K][N] fp32 -> Wt[N][K] fp16
// ---------------------------------------------------------------------------
__global__ __launch_bounds__(256) void wconv_kernel(
    const float* __restrict__ W0, const float* __restrict__ W1,
    const float* __restrict__ W2, const float* __restrict__ W3)
{
    __shared__ float tile[32][33];
    int mat = blockIdx.z;
    const float* W = (mat == 0 ? W0 : mat == 1 ? W1 : mat == 2 ? W2 : W3);
    __half* oh = g_wth + (size_t)mat * ISZ * ISZ;

    int nt = blockIdx.x * 32, kt = blockIdx.y * 32;
    int tx = threadIdx.x & 31, ty = threadIdx.x >> 5;   // 32 x 8

#pragma unroll
    for (int i = 0; i < 4; i++)
        tile[ty + i * 8][tx] = W[(size_t)(kt + ty + i * 8) * ISZ + nt + tx];
    __syncthreads();
#pragma unroll
    for (int i = 0; i < 4; i++) {
        int n = nt + ty + i * 8;
        oh[(size_t)n * ISZ + kt + tx] = __float2half_rn(tile[tx][ty + i * 8]);
    }
}

// ---------------------------------------------------------------------------
// Tensor-core GEMM via mma.sync, single fp16 A and B, 3-stage cp.async.
// C = A[M,K] @ B[N,K]^T + bias, * mask.  blockIdx.z selects operand set.
// ---------------------------------------------------------------------------
#define GM 4096
#define GN 1024
#define GK 1024
#define KST 64
#define NST (GK / KST)          // 16 stages
#define SK  72                  // smem stride in halves
#define PBY (128 * SK * 2)      // bytes per piece: 18432
#define STB (2 * PBY)           // per stage: 36864 (A, B)
#define GSMEM (3 * STB)         // 110592 (3-stage)

__global__ __launch_bounds__(256, 1) void gemm_mma(
    const __half* __restrict__ Abase, const __half* __restrict__ Bbase,
    const float* __restrict__ bias0, const float* __restrict__ mask0, float* __restrict__ C0,
    const float* __restrict__ bias1, const float* __restrict__ mask1, float* __restrict__ C1,
    const float* __restrict__ bias2, const float* __restrict__ mask2, float* __restrict__ C2)
{
    extern __shared__ __align__(128) char smc[];
    uint32_t sb = smem_u32(smc);

    int tid = threadIdx.x;
    int wid = tid >> 5, lane = tid & 31;
    int bn = blockIdx.x * 128, bm = blockIdx.y * 128;
    int z = blockIdx.z;
    int warp_m = (wid >> 2) * 64;
    int warp_n = (wid & 3) * 32;

    const float* bias = (z == 0) ? bias0 : (z == 1) ? bias1 : bias2;
    const float* mask = (z == 0) ? mask0 : (z == 1) ? mask1 : mask2;
    float* C = (z == 0) ? C0 : (z == 1) ? C1 : C2;

    const size_t TA = (size_t)ROWS * ISZ;   // A z-stride
    const size_t TB = (size_t)ISZ * ISZ;    // B z-stride
    const __half* srcs[2] = {
        Abase + (size_t)z * TA + (size_t)bm * GK,
        Bbase + (size_t)z * TB + (size_t)bn * GK };

    auto load_stage = [&](int t, int s) {
        int k0 = t * KST;
        uint32_t dbase = sb + s * STB;
#pragma unroll
        for (int buf = 0; buf < 2; buf++) {
#pragma unroll
            for (int i = 0; i < 4; i++) {
                int chunk = tid + i * 256;          // 0..1023
                int r = chunk >> 3, c = chunk & 7;  // row, 16B chunk
                const void* src = srcs[buf] + (size_t)r * GK + k0 + c * 8;
                uint32_t dst = dbase + buf * PBY + r * (SK * 2) + c * 16;
                cp_async16(dst, src);
            }
        }
    };

    float acc[4][4][4];
#pragma unroll
    for (int i = 0; i < 4; i++)
#pragma unroll
        for (int j = 0; j < 4; j++)
#pragma unroll
            for (int r = 0; r < 4; r++) acc[i][j][r] = 0.f;

    int a_row = lane & 15;
    int a_kh  = (lane >> 4) * 16;
    int b_row = lane & 7;
    int b_kh  = ((lane >> 3) & 1) * 16;

    load_stage(0, 0); cp_commit();
    load_stage(1, 1); cp_commit();

    int sbuf_idx = 0;
    for (int t = 0; t < NST; t++) {
        if (t < NST - 1) cp_wait1();    // stage t complete (t+1 may be in flight)
        else             cp_wait0();
        __syncthreads();                 // data visible; all warps done with t-1
        if (t + 2 < NST) {
            int s2 = (sbuf_idx + 2 >= 3) ? sbuf_idx + 2 - 3 : sbuf_idx + 2;
            load_stage(t + 2, s2);       // overwrites buffer of stage t-1 (safe)
            cp_commit();
        }

        uint32_t st = sb + sbuf_idx * STB;
#pragma unroll
        for (int k16 = 0; k16 < 4; k16++) {
            uint32_t kb = k16 * 32;
            uint32_t ah[4][4], bf[4][2];
#pragma unroll
            for (int mt = 0; mt < 4; mt++) {
                uint32_t ra = (warp_m + mt * 16 + a_row) * (SK * 2) + kb + a_kh;
                ldsm_x4(ah[mt][0], ah[mt][1], ah[mt][2], ah[mt][3], st + ra);
            }
#pragma unroll
            for (int nt = 0; nt < 4; nt++) {
                uint32_t rb = (warp_n + nt * 8 + b_row) * (SK * 2) + kb + b_kh;
                ldsm_x2(bf[nt][0], bf[nt][1], st + PBY + rb);
            }
#pragma unroll
            for (int mt = 0; mt < 4; mt++)
#pragma unroll
                for (int nt = 0; nt < 4; nt++)
                    mma_f16(acc[mt][nt], ah[mt], bf[nt]);
        }
        sbuf_idx = (sbuf_idx + 1 >= 3) ? 0 : sbuf_idx + 1;
    }

#pragma unroll
    for (int mt = 0; mt < 4; mt++) {
        int r0 = bm + warp_m + mt * 16 + (lane >> 2);
        int r1 = r0 + 8;
        float mk0 = mask[r0], mk1 = mask[r1];
        float* c0 = C + (size_t)r0 * GN;
        float* c1 = C + (size_t)r1 * GN;
#pragma unroll
        for (int nt = 0; nt < 4; nt++) {
            int col = bn + warp_n + nt * 8 + (lane & 3) * 2;
            float2 o0, o1;
            o0.x = (acc[mt][nt][0] + bias[col + 0]) * mk0;
            o0.y = (acc[mt][nt][1] + bias[col + 1]) * mk0;
            o1.x = (acc[mt][nt][2] + bias[col + 0]) * mk1;
            o1.y = (acc[mt][nt][3] + bias[col + 1]) * mk1;
            *(float2*)(c0 + col) = o0;
            *(float2*)(c1 + col) = o1;
        }
    }
}

// ---------------------------------------------------------------------------
// Flash attention on tensor cores (fp16 mma.sync), 2 CTAs/SM.
// Q split hi/lo (scores); P single fp16 (PV).  K,V single fp16.
// ---------------------------------------------------------------------------
#define AST 72   // smem row stride in halves (144 B)
#define ATTN_SMEM ((2 * 128 * AST + 2 * 64 * AST) * 2)   // 55296 bytes

__global__ __launch_bounds__(256, 2) void attn_mma(
    const float* __restrict__ Qw, const float* __restrict__ Kw,
    const float* __restrict__ Vw)
{
    extern __shared__ __align__(16) __half ash[];
    __half* Qh = ash;                         // [128][AST] persistent
    __half* Ql = ash + 128 * AST;             // [128][AST] persistent
    __half* Ks = ash + 2 * 128 * AST;         // [64][AST]
    __half* Vs = ash + 2 * 128 * AST + 64 * AST;

    int tid = threadIdx.x;
    int wid = tid >> 5, lane = tid & 31;
    int qb = (int)(gridDim.x - 1 - blockIdx.x);   // heavy blocks first
    int bh = blockIdx.y;
    int b = bh >> 4, h = bh & 15;

    size_t tokQ = (size_t)b * SEQ + qb * 128;
    int colBase = h * HDIM;

#pragma unroll
    for (int i = 0; i < 8; i++) {
        int p = tid + i * 256;
        int r = p >> 4, c4 = p & 15;
        float4 qv = *(const float4*)(Qw + (tokQ + r) * ISZ + colBase + c4 * 4);
        float y[4] = { qv.x * 0.125f, qv.y * 0.125f, qv.z * 0.125f, qv.w * 0.125f };
#pragma unroll
        for (int e = 0; e < 4; e++) {
            __half hi = __float2half_rn(y[e]);
            Qh[r * AST + c4 * 4 + e] = hi;
            Ql[r * AST + c4 * 4 + e] = __float2half_rn(y[e] - __half2float(hi));
        }
    }
    __syncthreads();

    float O[8][4];
#pragma unroll
    for (int nt = 0; nt < 8; nt++)
#pragma unroll
        for (int e = 0; e < 4; e++) O[nt][e] = 0.f;
    float mrow[2] = { -3e38f, -3e38f };
    float lrow[2] = { 0.f, 0.f };

    uint32_t qb0 = smem_u32(Qh);
    uint32_t qb1 = smem_u32(Ql);
    uint32_t ksb = smem_u32(Ks);
    uint32_t vsb = smem_u32(Vs);
    int a_row = lane & 15;
    int a_kh  = (lane >> 4) * 16;
    int b_row = lane & 7;
    int b_kh  = ((lane >> 3) & 1) * 16;

    int nkt = 2 * qb + 2;
    for (int kt = 0; kt < nkt; kt++) {
        if (kt > 0) __syncthreads();
        size_t tokK = (size_t)b * SEQ + kt * 64;
#pragma unroll
        for (int i = 0; i < 4; i++) {
            int p = tid + i * 256;
            int r = p >> 4, c4 = p & 15;
            float4 kv = *(const float4*)(Kw + (tokK + r) * ISZ + colBase + c4 * 4);
            *(uint32_t*)(Ks + r * AST + c4 * 4)     = h2pack(kv.x, kv.y);
            *(uint32_t*)(Ks + r * AST + c4 * 4 + 2) = h2pack(kv.z, kv.w);
            float4 vv = *(const float4*)(Vw + (tokK + r) * ISZ + colBase + c4 * 4);
            *(uint32_t*)(Vs + r * AST + c4 * 4)     = h2pack(vv.x, vv.y);
            *(uint32_t*)(Vs + r * AST + c4 * 4 + 2) = h2pack(vv.z, vv.w);
        }
        __syncthreads();

        float S[8][4];
#pragma unroll
        for (int nt = 0; nt < 8; nt++)
#pragma unroll
            for (int e = 0; e < 4; e++) S[nt][e] = 0.f;

#pragma unroll
        for (int j = 0; j < 4; j++) {
            uint32_t qoff = (wid * 16 + a_row) * (AST * 2) + j * 32 + a_kh;
            uint32_t qfh[4], qfl[4];
            ldsm_x4(qfh[0], qfh[1], qfh[2], qfh[3], qb0 + qoff);
            ldsm_x4(qfl[0], qfl[1], qfl[2], qfl[3], qb1 + qoff);
#pragma unroll
            for (int nt = 0; nt < 8; nt++) {
                uint32_t kf[2];
                ldsm_x2(kf[0], kf[1], ksb + (nt * 8 + b_row) * (AST * 2) + j * 32 + b_kh);
                mma_f16(S[nt], qfh, kf);
                mma_f16(S[nt], qfl, kf);
            }
        }

        if (kt >= 2 * qb) {
            int Rb = qb * 128 + wid * 16 + (lane >> 2);
#pragma unroll
            for (int nt = 0; nt < 8; nt++)
#pragma unroll
                for (int e = 0; e < 4; e++) {
                    int R = Rb + (e >> 1) * 8;
                    int C = kt * 64 + nt * 8 + 2 * (lane & 3) + (e & 1);
                    if (C > R) S[nt][e] = -3e38f;
                }
        }

#pragma unroll
        for (int hh = 0; hh < 2; hh++) {
            float mx = -3e38f;
#pragma unroll
            for (int nt = 0; nt < 8; nt++) {
                mx = fmaxf(mx, S[nt][2 * hh]);
                mx = fmaxf(mx, S[nt][2 * hh + 1]);
            }
            mx = fmaxf(mx, __shfl_xor_sync(0xffffffffu, mx, 1));
            mx = fmaxf(mx, __shfl_xor_sync(0xffffffffu, mx, 2));

            float mnew = fmaxf(mrow[hh], mx);
            float corr = __expf(mrow[hh] - mnew);
            float ts = 0.f;
#pragma unroll
            for (int nt = 0; nt < 8; nt++) {
                float p0 = __expf(S[nt][2 * hh]     - mnew);
                float p1 = __expf(S[nt][2 * hh + 1] - mnew);
                S[nt][2 * hh]     = p0;
                S[nt][2 * hh + 1] = p1;
                ts += p0 + p1;
            }
            ts += __shfl_xor_sync(0xffffffffu, ts, 1);
            ts += __shfl_xor_sync(0xffffffffu, ts, 2);

            lrow[hh] = lrow[hh] * corr + ts;
            mrow[hh] = mnew;
#pragma unroll
            for (int nt = 0; nt < 8; nt++) {
                O[nt][2 * hh]     *= corr;
                O[nt][2 * hh + 1] *= corr;
            }
        }

        // ---- O += P @ V  (P single fp16) ----
#pragma unroll
        for (int j = 0; j < 4; j++) {
            uint32_t ph[4];
#pragma unroll
            for (int r = 0; r < 4; r++) {
                int nt = 2 * j + (r >> 1);
                int e0 = (r & 1) * 2;
                ph[r] = h2pack(S[nt][e0], S[nt][e0 + 1]);
            }
#pragma unroll
            for (int nt = 0; nt < 8; nt++) {
                uint32_t vf[2];
                ldsm_x2t(vf[0], vf[1], vsb + (j * 16 + (lane & 15)) * (AST * 2) + nt * 16);
                mma_f16(O[nt], ph, vf);
            }
        }
    }

    // ---- epilogue: normalize, fp16 for the Wo GEMM ----
#pragma unroll
    for (int hh = 0; hh < 2; hh++) {
        float inv = 1.f / lrow[hh];
        size_t tok = tokQ + wid * 16 + (lane >> 2) + 8 * hh;
#pragma unroll
        for (int nt = 0; nt < 8; nt++) {
            int col = colBase + nt * 8 + 2 * (lane & 3);
            *(__half2*)(g_ao + tok * ISZ + col) =
                __floats2half2_rn(O[nt][2 * hh] * inv, O[nt][2 * hh + 1] * inv);
        }
    }
}

// ---------------------------------------------------------------------------
// Launch
// ---------------------------------------------------------------------------
template <typename T> static T* symaddr(const void* sym) {
    void* p; cudaGetSymbolAddress(&p, sym); return (T*)p;
}

extern "C" void kernel_launch(void* const* d_in, const int* in_sizes, int n_in,
                              void* d_out, int out_size)
{
    const float* q       = (const float*)d_in[0];
    const float* k       = (const float*)d_in[1];
    const float* v       = (const float*)d_in[2];
    const float* q_mask  = (const float*)d_in[3];
    const float* kv_mask = (const float*)d_in[4];
    const float* ln_g    = (const float*)d_in[6];
    const float* ln_b    = (const float*)d_in[7];
    const float* Wq      = (const float*)d_in[8];
    const float* bq      = (const float*)d_in[9];
    const float* Wk      = (const float*)d_in[10];
    const float* bk      = (const float*)d_in[11];
    const float* Wv      = (const float*)d_in[12];
    const float* bv      = (const float*)d_in[13];
    const float* Wo      = (const float*)d_in[14];
    const float* bo      = (const float*)d_in[15];
    float* out = (float*)d_out;

    __half* xh  = symaddr<__half>(g_xh);
    __half* wth = symaddr<__half>(g_wth);
    float*  qw  = symaddr<float>(g_qw);
    float*  kw  = symaddr<float>(g_kw);
    float*  vw  = symaddr<float>(g_vw);
    __half* ao  = symaddr<__half>(g_ao);

    const size_t WSZ = (size_t)ISZ * ISZ;

    // 1) LayerNorm -> fp16
    ln3_kernel<<<3 * ROWS, 256>>>(q, k, v, ln_g, ln_b);

    // 2) Weight transpose -> fp16
    wconv_kernel<<<dim3(32, 32, 4), 256>>>(Wq, Wk, Wv, Wo);

    // 3) QKV projections: one fused launch (z = q,k,v), 3-stage pipeline
    cudaFuncSetAttribute(gemm_mma,
                         cudaFuncAttributeMaxDynamicSharedMemorySize, GSMEM);
    dim3 qkvgrid(GN / 128, GM / 128, 3);
    gemm_mma<<<qkvgrid, 256, GSMEM>>>(
        xh, wth,
        bq, q_mask,  qw,
        bk, kv_mask, kw,
        bv, kv_mask, vw);

    // 4) Flash attention on tensor cores -> fp16 (2 CTAs/SM)
    cudaFuncSetAttribute(attn_mma,
                         cudaFuncAttributeMaxDynamicSharedMemorySize, ATTN_SMEM);
    dim3 agrid(SEQ / 128, BATCH * NHEAD);
    attn_mma<<<agrid, 256, ATTN_SMEM>>>(qw, kw, vw);

    // 5) Output projection straight into d_out (z grid = 1)
    dim3 ogrid(GN / 128, GM / 128, 1);
    gemm_mma<<<ogrid, 256, GSMEM>>>(
        ao, wth + 3 * WSZ,
        bo, kv_mask, out,
        bo, kv_mask, out,
        bo, kv_mask, out);
}